// round 13
// baseline (speedup 1.0000x reference)
#include <cuda_runtime.h>
#include <cstdint>
#include <math.h>

#define FULLMASK 0xffffffffu
#define NENT   8192
#define EMB    256
#define ARDIM  1024
#define UTYPE  233
#define CL     8
#define TPB    512

// ---- smem layout (float offsets) ----
#define OFF_KEYS   0        // 32768
#define OFF_WA1    32768    // 8192
#define OFF_W3T    40960    // 4096
#define OFF_PART   45056    // 2048
#define OFF_WG     47104    // 8448 = 4 gates x 32 rows x stride 66
#define OFF_MASK   55552    // 1024
#define OFF_MBK    56576    // 256
#define OFF_ARS    56832    // 128
#define OFF_C0     56960    // 256
#define OFF_A      57216    // 256
#define OFF_X      57472    // 64
#define OFF_Q      57536    // 32
#define OFF_H      57568    // 32
#define OFF_QN     57600    // 32
#define OFF_G      57632    // 128
#define OFF_CENT   57760    // 32
#define OFF_MB     57792    // 32
#define OFF_RED    57824    // 48
#define OFF_BIAS   57872    // 224
#define OFF_SCAL   58096    // 4
#define OFF_BARA   58100    // u64 (8B aligned: byte 232400)
#define OFF_BARB   58102    // u64
#define SMEM_FLOATS 58104
#define SMEM_BYTES (SMEM_FLOATS * 4)

static __device__ float g_keys[32 * NENT];   // k-major

// ---------------- helpers ----------------
__device__ __forceinline__ uint32_t smem_u32(const void* p) {
    return (uint32_t)__cvta_generic_to_shared(p);
}
__device__ __forceinline__ uint32_t mapa_rank(uint32_t addr, uint32_t rank) {
    uint32_t r;
    asm volatile("mapa.shared::cluster.u32 %0, %1, %2;" : "=r"(r) : "r"(addr), "r"(rank));
    return r;
}
__device__ __forceinline__ void st_remote_f32(uint32_t addr, float v) {
    asm volatile("st.shared::cluster.f32 [%0], %1;" :: "r"(addr), "f"(v));
}
__device__ __forceinline__ void cluster_sync_all() {
    asm volatile("barrier.cluster.arrive.aligned;" ::: "memory");
    asm volatile("barrier.cluster.wait.aligned;" ::: "memory");
}
__device__ __forceinline__ uint32_t ctarank() {
    uint32_t r;
    asm("mov.u32 %0, %%cluster_ctarank;" : "=r"(r));
    return r;
}
__device__ __forceinline__ void mbar_init(uint32_t addr, uint32_t cnt) {
    asm volatile("mbarrier.init.shared.b64 [%0], %1;" :: "r"(addr), "r"(cnt) : "memory");
}
__device__ __forceinline__ void mbar_arrive_remote(uint32_t addr) {
    asm volatile("mbarrier.arrive.release.cluster.shared::cluster.b64 _, [%0];"
                 :: "r"(addr) : "memory");
}
__device__ __forceinline__ void mbar_wait(uint32_t addr, uint32_t parity) {
    uint32_t done;
    asm volatile(
        "{\n\t"
        ".reg .pred p;\n\t"
        "mbarrier.try_wait.parity.acquire.cluster.shared::cta.b64 p, [%1], %2;\n\t"
        "selp.b32 %0, 1, 0, p;\n\t"
        "}"
        : "=r"(done) : "r"(addr), "r"(parity) : "memory");
    if (!done) {
        asm volatile(
            "{\n\t"
            ".reg .pred P1;\n\t"
            "WAIT_LOOP_%=:\n\t"
            "mbarrier.try_wait.parity.acquire.cluster.shared::cta.b64 P1, [%0], %1, 0x989680;\n\t"
            "@P1 bra.uni WAIT_DONE_%=;\n\t"
            "bra.uni WAIT_LOOP_%=;\n\t"
            "WAIT_DONE_%=:\n\t"
            "}"
            :: "r"(addr), "r"(parity) : "memory");
    }
}
__device__ __forceinline__ float wsum(float x) {
#pragma unroll
    for (int o = 16; o > 0; o >>= 1) x += __shfl_xor_sync(FULLMASK, x, o);
    return x;
}
__device__ __forceinline__ void argmax_red(float& v, float& idx) {
#pragma unroll
    for (int o = 16; o > 0; o >>= 1) {
        float ov = __shfl_xor_sync(FULLMASK, v, o);
        float oi = __shfl_xor_sync(FULLMASK, idx, o);
        if (ov > v || (ov == v && oi < idx)) { v = ov; idx = oi; }
    }
}
__device__ __forceinline__ float fsig(float x) {
    return __fdividef(1.f, 1.f + __expf(-x));
}
__device__ __forceinline__ float ftanh(float x) {
    x = fminf(fmaxf(x, -15.f), 15.f);
    float e = __expf(2.f * x);
    return __fdividef(e - 1.f, e + 1.f);
}

// ---------------- fused zero-fill + keys ----------------
__global__ void __launch_bounds__(256) zk_kernel(const float4* __restrict__ Wk,
                                                 const float* __restrict__ bk,
                                                 const float4* __restrict__ enc,
                                                 float4* __restrict__ out4,
                                                 int total4) {
    if (blockIdx.x < 1024) {
        int g = blockIdx.x * 256 + threadIdx.x;
        int e = g >> 5;
        int lane = g & 31;
        const float4* er = enc + (size_t)e * 64;
        const float4* wr = Wk + (size_t)lane * 64;
        float acc = 0.f;
#pragma unroll 8
        for (int j = 0; j < 64; j++) {
            float4 a = er[j];
            float4 b = wr[j];
            acc += a.x * b.x + a.y * b.y + a.z * b.z + a.w * b.w;
        }
        g_keys[lane * NENT + e] = acc + bk[lane];
    } else {
        const float4 z = make_float4(0.f, 0.f, 0.f, 0.f);
        int nz = (gridDim.x - 1024) * 256;
        for (int i = (blockIdx.x - 1024) * 256 + threadIdx.x; i < total4; i += nz)
            __stcs(&out4[i], z);
    }
}

// ---------------- persistent sequential cluster kernel ----------------
__global__ void __cluster_dims__(CL, 1, 1) __launch_bounds__(TPB, 1)
seq_kernel(float* __restrict__ out,
           const int* __restrict__ p_steps,
           const float* __restrict__ entity_mask,
           const float* __restrict__ ar_in,
           const float* __restrict__ utype,
           const float* __restrict__ W_fe, const float* __restrict__ b_fe,
           const float* __restrict__ W_a0, const float* __restrict__ b_a0,
           const float* __restrict__ W_a1, const float* __restrict__ b_a1,
           const float* __restrict__ W_f,  const float* __restrict__ b_f,
           const float* __restrict__ W_i0, const float* __restrict__ b_i0,
           const float* __restrict__ W_i1, const float* __restrict__ b_i1,
           const float* __restrict__ W_o,  const float* __restrict__ b_o,
           const float* __restrict__ ln_g, const float* __restrict__ ln_b,
           const float* __restrict__ W_a3, const float* __restrict__ b_a3)
{
    extern __shared__ float sm[];
    const int tid  = threadIdx.x;
    const int lane = tid & 31;
    const int wid  = tid >> 5;
    const uint32_t rank = ctarank();
    const uint32_t smbase = smem_u32(sm);

    int raw = p_steps[0];
    int stepsv = (raw >= 0 && raw <= 100000) ? raw : (int)__int_as_float(raw);
    int steps = stepsv < 64 ? stepsv : 64;
    if (steps < 0) steps = 0;

    // ---- prologue ----
#pragma unroll
    for (int k = 0; k < 32; k++) {
        sm[OFF_KEYS + k * 1024 + tid]       = g_keys[k * NENT + (int)rank * 1024 + tid];
        sm[OFF_KEYS + k * 1024 + 512 + tid] = g_keys[k * NENT + (int)rank * 1024 + 512 + tid];
    }
    sm[OFF_MASK + tid]       = entity_mask[(int)rank * 1024 + tid];
    sm[OFF_MASK + 512 + tid] = entity_mask[(int)rank * 1024 + 512 + tid];
#pragma unroll
    for (int i = 0; i < 16; i++)
        sm[OFF_WA1 + i * 512 + tid] = W_a1[i * 512 + tid];
#pragma unroll
    for (int i = 0; i < 8; i++) {
        int idx = tid + i * 512;   // idx = k*128 + t
        sm[OFF_W3T + idx] = W_a3[((int)rank * 128 + (idx & 127)) * 32 + (idx >> 7)];
    }
    {   // gate weights, padded layout: [g][row stride 66][half*33 + col31]
        const float* gw4[4] = { W_f, W_i0, W_i1, W_o };
        for (int idx = tid; idx < 4 * 2048; idx += TPB) {
            int g = idx >> 11, rem = idx & 2047, r = rem >> 6, c = rem & 63;
            sm[OFF_WG + g * 2112 + r * 66 + (c >> 5) * 33 + (c & 31)] = gw4[g][rem];
        }
    }
    float ba3 = 0.f;
    if (tid < 128) {
        sm[OFF_ARS + tid] = ar_in[(int)rank * 128 + tid];
        ba3 = b_a3[(int)rank * 128 + tid];
    }
    if (tid < 32) {
        sm[OFF_Q + tid] = 0.f; sm[OFF_H + tid] = 0.f;
        sm[OFF_BIAS +       tid] = b_a1[tid];
        sm[OFF_BIAS + 32  + tid] = b_f[tid];
        sm[OFF_BIAS + 64  + tid] = b_i0[tid];
        sm[OFF_BIAS + 96  + tid] = b_i1[tid];
        sm[OFF_BIAS + 128 + tid] = b_o[tid];
        sm[OFF_BIAS + 160 + tid] = ln_g[tid];
        sm[OFF_BIAS + 192 + tid] = ln_b[tid];
    }
    if (tid == 0) {
        sm[OFF_SCAL + 3] = 0.f;
        mbar_init(smbase + OFF_BARA * 4u, 8);
        mbar_init(smbase + OFF_BARB * 4u, 8);
    }
    for (int rr = 0; rr < 16; rr++) {
        int row = wid * 16 + rr;
        float acc = 0.f;
#pragma unroll
        for (int i = 0; i < 8; i++) {
            int j = lane + (i << 5);
            if (j < UTYPE) acc += W_fe[row * UTYPE + j] * utype[j];
        }
        acc = wsum(acc);
        if (lane == 0) sm[OFF_C0 + row] = b_a0[row] + fmaxf(0.f, acc + b_fe[row]);
    }
    // register-pinned W_a0: thread owns row (tid>>1), half (tid&1)
    const int row2 = tid >> 1;
    const int half = tid & 1;
    float4 w16[16];
    {
        const float4* wp = (const float4*)(W_a0 + (size_t)row2 * ARDIM + (int)rank * 128 + half * 64);
#pragma unroll
        for (int j = 0; j < 16; j++) w16[j] = wp[j];
    }
    uint32_t pd0 = mapa_rank(smbase + (OFF_PART + (int)rank * 256) * 4u, (uint32_t)(half * 4 + 0));
    uint32_t pd1 = mapa_rank(smbase + (OFF_PART + (int)rank * 256) * 4u, (uint32_t)(half * 4 + 1));
    uint32_t pd2 = mapa_rank(smbase + (OFF_PART + (int)rank * 256) * 4u, (uint32_t)(half * 4 + 2));
    uint32_t pd3 = mapa_rank(smbase + (OFF_PART + (int)rank * 256) * 4u, (uint32_t)(half * 4 + 3));
    uint32_t mb_dst = mapa_rank(smbase + OFF_MB * 4u, (uint32_t)(lane & 7));
    // remote mbarrier targets (lanes/tid < 8 use these)
    uint32_t barA_rt = mapa_rank(smbase + OFF_BARA * 4u, (uint32_t)(tid & 7));
    uint32_t barB_rt = mapa_rank(smbase + OFF_BARB * 4u, (uint32_t)(tid & 7));
    uint32_t barA_lo = smbase + OFF_BARA * 4u;
    uint32_t barB_lo = smbase + OFF_BARB * 4u;
    cluster_sync_all();   // publishes mbarrier inits + prologue smem

    // ---- sequential steps ----
    for (int step = 0; step < steps; ++step) {
        uint32_t par = (uint32_t)(step & 1);
        __syncthreads();

        // S0: row-per-thread-pair GEMV from registers, 1 shfl, 4-rank scatter
        {
            const float4* ap = ((const float4*)(sm + OFF_ARS)) + (half << 4);
            float a0 = 0.f, a1 = 0.f, a2 = 0.f, a3 = 0.f;
#pragma unroll
            for (int j = 0; j < 16; j += 4) {
                float4 x0 = ap[j], x1 = ap[j + 1], x2 = ap[j + 2], x3 = ap[j + 3];
                a0 += w16[j].x     * x0.x + w16[j].y     * x0.y + w16[j].z     * x0.z + w16[j].w     * x0.w;
                a1 += w16[j + 1].x * x1.x + w16[j + 1].y * x1.y + w16[j + 1].z * x1.z + w16[j + 1].w * x1.w;
                a2 += w16[j + 2].x * x2.x + w16[j + 2].y * x2.y + w16[j + 2].z * x2.z + w16[j + 2].w * x2.w;
                a3 += w16[j + 3].x * x3.x + w16[j + 3].y * x3.y + w16[j + 3].z * x3.z + w16[j + 3].w * x3.w;
            }
            float acc = (a0 + a1) + (a2 + a3);
            acc += __shfl_xor_sync(FULLMASK, acc, 1);
            uint32_t off = (uint32_t)row2 * 4u;
            st_remote_f32(pd0 + off, acc);
            st_remote_f32(pd1 + off, acc);
            st_remote_f32(pd2 + off, acc);
            st_remote_f32(pd3 + off, acc);
        }
        // sync A (mbarrier all-to-all)
        __syncthreads();
        if (tid < 8) mbar_arrive_remote(barA_rt);
        mbar_wait(barA_lo, par);

        // S1 (replicated): i0 -> relu -> i1 -> gates -> LSTM -> qn
        bool active = (sm[OFF_SCAL + 3] == 0.f);
        if (tid < 256) {
            float s = 0.f;
#pragma unroll
            for (int r = 0; r < 8; r++) s += sm[OFF_PART + r * 256 + tid];
            sm[OFF_A + tid] = fmaxf(0.f, s + sm[OFF_C0 + tid]);
        }
        __syncthreads();
        {   // i1: 2 rows/warp, dots first, then interleaved full reduction chains
            float acc0, acc1;
            {
                const float4* a4 = (const float4*)(sm + OFF_A);
                float4 x0 = a4[lane * 2], x1 = a4[lane * 2 + 1];
                const float4* wr0 = (const float4*)(sm + OFF_WA1 + (wid * 2) * EMB);
                const float4* wr1 = (const float4*)(sm + OFF_WA1 + (wid * 2 + 1) * EMB);
                float4 p0 = wr0[lane * 2], p1 = wr0[lane * 2 + 1];
                float4 q0 = wr1[lane * 2], q1 = wr1[lane * 2 + 1];
                acc0 = p0.x * x0.x + p0.y * x0.y + p0.z * x0.z + p0.w * x0.w
                     + p1.x * x1.x + p1.y * x1.y + p1.z * x1.z + p1.w * x1.w;
                acc1 = q0.x * x0.x + q0.y * x0.y + q0.z * x0.z + q0.w * x0.w
                     + q1.x * x1.x + q1.y * x1.y + q1.z * x1.z + q1.w * x1.w;
            }
#pragma unroll
            for (int o = 16; o > 0; o >>= 1) {
                acc0 += __shfl_xor_sync(FULLMASK, acc0, o);
                acc1 += __shfl_xor_sync(FULLMASK, acc1, o);
            }
            if (lane == 0) {
                sm[OFF_X + wid * 2]     = fmaxf(0.f, acc0 + sm[OFF_BIAS + wid * 2]);
                sm[OFF_X + wid * 2 + 1] = fmaxf(0.f, acc1 + sm[OFF_BIAS + wid * 2 + 1]);
            }
        }
        if (wid == 1) sm[OFF_X + 32 + lane] = sm[OFF_Q + lane];
        __syncthreads();
        // gates: 128 outputs over 256 threads, padded conflict-free layout, 1 shfl
        if (tid < 256) {
            int o = tid >> 1, hf = tid & 1;
            int g = o >> 5, row = o & 31;
            const float* wp = sm + OFF_WG + g * 2112 + row * 66 + hf * 33;
            const float* xp = sm + OFF_X + hf * 32;
            float a0 = 0.f, a1 = 0.f, a2 = 0.f, a3 = 0.f;
#pragma unroll
            for (int j = 0; j < 32; j += 4) {
                a0 += wp[j]     * xp[j];
                a1 += wp[j + 1] * xp[j + 1];
                a2 += wp[j + 2] * xp[j + 2];
                a3 += wp[j + 3] * xp[j + 3];
            }
            float acc = (a0 + a1) + (a2 + a3);
            acc += __shfl_xor_sync(FULLMASK, acc, 1);
            if (hf == 0) sm[OFF_G + g * 32 + row] = acc + sm[OFF_BIAS + 32 + g * 32 + row];
        }
        __syncthreads();
        if (wid == 0) {
            float g = sm[OFF_BIAS + 160 + lane], b = sm[OFF_BIAS + 192 + lane];
            float gF = sm[OFF_G + lane], g0v = sm[OFF_G + 32 + lane];
            float g1v = sm[OFF_G + 64 + lane], gO = sm[OFF_G + 96 + lane];
            float xF = fsig(gF);
            float xR = fsig(g0v) * ftanh(g1v);
            float xO = fsig(gO);
            float aF = xF, aR = xR, aO = xO;
            float qF = xF * xF, qR = xR * xR, qO = xO * xO;
#pragma unroll
            for (int o = 16; o > 0; o >>= 1) {
                aF += __shfl_xor_sync(FULLMASK, aF, o);
                aR += __shfl_xor_sync(FULLMASK, aR, o);
                aO += __shfl_xor_sync(FULLMASK, aO, o);
                qF += __shfl_xor_sync(FULLMASK, qF, o);
                qR += __shfl_xor_sync(FULLMASK, qR, o);
                qO += __shfl_xor_sync(FULLMASK, qO, o);
            }
            const float inv32 = 1.f / 32.f;
            float mF = aF * inv32, vF = qF * inv32 - mF * mF;
            float mR = aR * inv32, vR = qR * inv32 - mR * mR;
            float mO = aO * inv32, vO = qO * inv32 - mO * mO;
            float forget = (xF - mF) * rsqrtf(vF + 1e-5f) * g + b;
            float rem    = (xR - mR) * rsqrtf(vR + 1e-5f) * g + b;
            float outg   = (xO - mO) * rsqrtf(vO + 1e-5f) * g + b;
            float hn = rem + forget * sm[OFF_H + lane];
            float qn = ftanh(hn) * outg;
            sm[OFF_QN + lane] = qn;
            if (active) { sm[OFF_Q + lane] = qn; sm[OFF_H + lane] = hn; }
        }
        __syncthreads();

        // S2: 2 entities per thread + reductions + all-to-all mailbox
        float d0 = 0.f, d1 = 0.f;
#pragma unroll
        for (int k = 0; k < 32; k++) {
            float q = sm[OFF_QN + k];
            d0 += q * sm[OFF_KEYS + k * 1024 + tid];
            d1 += q * sm[OFF_KEYS + k * 1024 + 512 + tid];
        }
        float v0 = __expf(__logf(1.f / (1.f + __expf(-d0))) * 1.25f);
        float v1 = __expf(__logf(1.f / (1.f + __expf(-d1))) * 1.25f);
        {
            float s = wsum(v0 + v1);
            float mv, mi;
            if (v1 > v0) { mv = v1; mi = (float)((int)rank * 1024 + 512 + tid); }
            else         { mv = v0; mi = (float)((int)rank * 1024 + tid); }
            argmax_red(mv, mi);
            if (lane == 0) {
                sm[OFF_RED + wid * 3 + 0] = s;
                sm[OFF_RED + wid * 3 + 1] = mv;
                sm[OFF_RED + wid * 3 + 2] = mi;
            }
        }
        __syncthreads();
        if (wid == 0) {
            float s2 = (lane < 16) ? sm[OFF_RED + lane * 3 + 0] : 0.f;
            float m2 = (lane < 16) ? sm[OFF_RED + lane * 3 + 1] : -INFINITY;
            float i2 = (lane < 16) ? sm[OFF_RED + lane * 3 + 2] : 1e9f;
#pragma unroll
            for (int o = 16; o > 0; o >>= 1) {
                s2 += __shfl_xor_sync(FULLMASK, s2, o);
                float ov = __shfl_xor_sync(FULLMASK, m2, o);
                float oi = __shfl_xor_sync(FULLMASK, i2, o);
                if (ov > m2 || (ov == m2 && oi < i2)) { m2 = ov; i2 = oi; }
            }
            int li = (int)i2 - (int)rank * 1024;
            float maskv = sm[OFF_MASK + li];
            float kv = sm[OFF_KEYS + lane * 1024 + li];
            uint32_t mbk_addr = smbase + (uint32_t)((OFF_MBK + (int)rank * 32 + lane) * 4);
#pragma unroll
            for (int rr = 0; rr < 8; rr++)
                st_remote_f32(mapa_rank(mbk_addr, (uint32_t)rr), kv);
            if (lane < 8) {
                st_remote_f32(mb_dst + ((uint32_t)rank) * 4u,        s2);
                st_remote_f32(mb_dst + (8u + (uint32_t)rank) * 4u,   m2);
                st_remote_f32(mb_dst + (16u + (uint32_t)rank) * 4u,  i2);
                st_remote_f32(mb_dst + (24u + (uint32_t)rank) * 4u,  maskv);
            }
        }
        // sync B (mbarrier all-to-all)
        __syncthreads();
        if (tid < 8) mbar_arrive_remote(barB_rt);
        mbar_wait(barB_lo, par);

        // S3 (replicated): pick, selection from local MBK, mask/flags
        if (wid == 0) {
            float s  = (lane < 8) ? sm[OFF_MB + lane]      : 0.f;
            float m  = (lane < 8) ? sm[OFF_MB + 8 + lane]  : -INFINITY;
            float ix = (lane < 8) ? sm[OFF_MB + 16 + lane] : 1e9f;
#pragma unroll
            for (int o = 16; o > 0; o >>= 1) {
                s += __shfl_xor_sync(FULLMASK, s, o);
                float ov = __shfl_xor_sync(FULLMASK, m, o);
                float oi = __shfl_xor_sync(FULLMASK, ix, o);
                if (ov > m || (ov == m && oi < ix)) { m = ov; ix = oi; }
            }
            float ssum = s;
            int pick = (int)ix;
            int wrank = pick >> 10;
            bool act2  = (sm[OFF_SCAL + 3] == 0.f);
            bool valid = (ssum != 0.f);
            float rowinv = (act2 && valid) ? 1.f / ssum : 0.f;
            float selv = sm[OFF_MBK + wrank * 32 + lane];
            float mean = wsum(selv) * (1.f / 32.f);
            float cen = selv - mean;
            bool nanfree = (__ballot_sync(FULLMASK, isnan(cen)) == 0u);
            bool hit = act2 && valid && (sm[OFF_MB + 24 + wrank] != 0.f);
            sm[OFF_CENT + lane] = cen;
            if (lane == 0) {
                sm[OFF_SCAL + 0] = rowinv;
                sm[OFF_SCAL + 2] = (hit && nanfree) ? 1.f : 0.f;
                if (hit) {
                    if (wrank == (int)rank) sm[OFF_MASK + (pick & 1023)] = 0.f;
                    if (rank == 0) out[(size_t)NENT * NENT + pick] = 1.f;
                }
                if (hit && !nanfree) sm[OFF_SCAL + 3] = 1.f;
            }
        }
        __syncthreads();

        // S4: row writes + local ar-slice update
        {
            float rowinv = sm[OFF_SCAL + 0];
            out[(size_t)step * NENT + (int)rank * 1024 + tid]       = v0 * rowinv;
            out[(size_t)step * NENT + (int)rank * 1024 + 512 + tid] = v1 * rowinv;
        }
        if (sm[OFF_SCAL + 2] != 0.f && tid < 128) {
            float d = 0.f;
#pragma unroll
            for (int k = 0; k < 32; k++) d += sm[OFF_W3T + k * 128 + tid] * sm[OFF_CENT + k];
            sm[OFF_ARS + tid] += fmaxf(0.f, d + ba3);
        }
    }

    __syncthreads();
    if (tid < 128)
        out[(size_t)NENT * NENT + NENT + (int)rank * 128 + tid] = sm[OFF_ARS + tid];
    // keep cluster alive until all CTAs stop issuing remote ops
    cluster_sync_all();
}

extern "C" void kernel_launch(void* const* d_in, const int* in_sizes, int n_in,
                              void* d_out, int out_size) {
    const float* utype = (const float*)d_in[0];
    const float* emask = (const float*)d_in[1];
    const float* enc   = (const float*)d_in[2];
    const float* ar    = (const float*)d_in[3];
    const float* W_fe  = (const float*)d_in[4];
    const float* b_fe  = (const float*)d_in[5];
    const float* W_k   = (const float*)d_in[6];
    const float* b_k   = (const float*)d_in[7];
    const float* W_a0  = (const float*)d_in[8];
    const float* b_a0  = (const float*)d_in[9];
    const float* W_a1  = (const float*)d_in[10];
    const float* b_a1  = (const float*)d_in[11];
    const float* W_f   = (const float*)d_in[12];
    const float* b_f   = (const float*)d_in[13];
    const float* W_i0  = (const float*)d_in[14];
    const float* b_i0  = (const float*)d_in[15];
    const float* W_i1  = (const float*)d_in[16];
    const float* b_i1  = (const float*)d_in[17];
    const float* W_o   = (const float*)d_in[18];
    const float* b_o   = (const float*)d_in[19];
    const float* ln_g  = (const float*)d_in[20];
    const float* ln_b  = (const float*)d_in[21];
    const float* W_a3  = (const float*)d_in[22];
    const float* b_a3  = (const float*)d_in[23];
    const int*   steps = (const int*)d_in[24];
    float* out = (float*)d_out;

    int total4 = out_size / 4;
    zk_kernel<<<1024 + 6144, 256>>>((const float4*)W_k, b_k, (const float4*)enc,
                                    (float4*)out, total4);
    cudaFuncSetAttribute(seq_kernel, cudaFuncAttributeMaxDynamicSharedMemorySize, SMEM_BYTES);
    seq_kernel<<<CL, TPB, SMEM_BYTES>>>(out, steps, emask, ar, utype,
                                        W_fe, b_fe, W_a0, b_a0, W_a1, b_a1,
                                        W_f, b_f, W_i0, b_i0, W_i1, b_i1,
                                        W_o, b_o, ln_g, ln_b, W_a3, b_a3);
}

// round 14
// speedup vs baseline: 1.0121x; 1.0121x over previous
#include <cuda_runtime.h>
#include <cstdint>
#include <math.h>

#define FULLMASK 0xffffffffu
#define NENT   8192
#define EMB    256
#define ARDIM  1024
#define UTYPE  233
#define CL     8
#define TPB    512

// ---- smem layout (float offsets) ----
#define OFF_KEYS   0        // 32768
#define OFF_WA1    32768    // 8192
#define OFF_W3T    40960    // 4096
#define OFF_PART   45056    // 2048
#define OFF_WG     47104    // 8448 = 4 gates x 32 rows x stride 66
#define OFF_MASK   55552    // 1024
#define OFF_MBK    56576    // 256
#define OFF_ARS    56832    // 128
#define OFF_C0     56960    // 256
#define OFF_A      57216    // 256
#define OFF_X      57472    // 64
#define OFF_Q      57536    // 32
#define OFF_H      57568    // 32
#define OFF_QN     57600    // 32
#define OFF_G      57632    // 128
#define OFF_CENT   57760    // 32
#define OFF_MB     57792    // 32
#define OFF_RED    57824    // 24 (8 warps x 3)
#define OFF_BIAS   57872    // 224
#define OFF_SCAL   58096    // 4
#define SMEM_FLOATS 58100
#define SMEM_BYTES (SMEM_FLOATS * 4)

static __device__ float g_keys[32 * NENT];   // k-major

// ---------------- helpers ----------------
__device__ __forceinline__ uint32_t smem_u32(const void* p) {
    return (uint32_t)__cvta_generic_to_shared(p);
}
__device__ __forceinline__ uint32_t mapa_rank(uint32_t addr, uint32_t rank) {
    uint32_t r;
    asm volatile("mapa.shared::cluster.u32 %0, %1, %2;" : "=r"(r) : "r"(addr), "r"(rank));
    return r;
}
__device__ __forceinline__ void st_remote_f32(uint32_t addr, float v) {
    asm volatile("st.shared::cluster.f32 [%0], %1;" :: "r"(addr), "f"(v));
}
__device__ __forceinline__ void cluster_sync_all() {
    asm volatile("barrier.cluster.arrive.aligned;" ::: "memory");
    asm volatile("barrier.cluster.wait.aligned;" ::: "memory");
}
__device__ __forceinline__ uint32_t ctarank() {
    uint32_t r;
    asm("mov.u32 %0, %%cluster_ctarank;" : "=r"(r));
    return r;
}
__device__ __forceinline__ float wsum(float x) {
#pragma unroll
    for (int o = 16; o > 0; o >>= 1) x += __shfl_xor_sync(FULLMASK, x, o);
    return x;
}
__device__ __forceinline__ void argmax_red(float& v, float& idx) {
#pragma unroll
    for (int o = 16; o > 0; o >>= 1) {
        float ov = __shfl_xor_sync(FULLMASK, v, o);
        float oi = __shfl_xor_sync(FULLMASK, idx, o);
        if (ov > v || (ov == v && oi < idx)) { v = ov; idx = oi; }
    }
}
__device__ __forceinline__ float fsig(float x) {
    return __fdividef(1.f, 1.f + __expf(-x));
}
__device__ __forceinline__ float ftanh(float x) {
    x = fminf(fmaxf(x, -15.f), 15.f);
    float e = __expf(2.f * x);
    return __fdividef(e - 1.f, e + 1.f);
}

// ---------------- fused zero-fill + keys ----------------
__global__ void __launch_bounds__(256) zk_kernel(const float4* __restrict__ Wk,
                                                 const float* __restrict__ bk,
                                                 const float4* __restrict__ enc,
                                                 float4* __restrict__ out4,
                                                 int total4) {
    if (blockIdx.x < 1024) {
        int g = blockIdx.x * 256 + threadIdx.x;
        int e = g >> 5;
        int lane = g & 31;
        const float4* er = enc + (size_t)e * 64;
        const float4* wr = Wk + (size_t)lane * 64;
        float acc = 0.f;
#pragma unroll 8
        for (int j = 0; j < 64; j++) {
            float4 a = er[j];
            float4 b = wr[j];
            acc += a.x * b.x + a.y * b.y + a.z * b.z + a.w * b.w;
        }
        g_keys[lane * NENT + e] = acc + bk[lane];
    } else {
        const float4 z = make_float4(0.f, 0.f, 0.f, 0.f);
        int nz = (gridDim.x - 1024) * 256;
        for (int i = (blockIdx.x - 1024) * 256 + threadIdx.x; i < total4; i += nz)
            __stcs(&out4[i], z);
    }
}

// ---------------- persistent sequential cluster kernel ----------------
__global__ void __cluster_dims__(CL, 1, 1) __launch_bounds__(TPB, 1)
seq_kernel(float* __restrict__ out,
           const int* __restrict__ p_steps,
           const float* __restrict__ entity_mask,
           const float* __restrict__ ar_in,
           const float* __restrict__ utype,
           const float* __restrict__ W_fe, const float* __restrict__ b_fe,
           const float* __restrict__ W_a0, const float* __restrict__ b_a0,
           const float* __restrict__ W_a1, const float* __restrict__ b_a1,
           const float* __restrict__ W_f,  const float* __restrict__ b_f,
           const float* __restrict__ W_i0, const float* __restrict__ b_i0,
           const float* __restrict__ W_i1, const float* __restrict__ b_i1,
           const float* __restrict__ W_o,  const float* __restrict__ b_o,
           const float* __restrict__ ln_g, const float* __restrict__ ln_b,
           const float* __restrict__ W_a3, const float* __restrict__ b_a3)
{
    extern __shared__ float sm[];
    const int tid  = threadIdx.x;
    const int lane = tid & 31;
    const int wid  = tid >> 5;
    const uint32_t rank = ctarank();
    const uint32_t smbase = smem_u32(sm);

    int raw = p_steps[0];
    int stepsv = (raw >= 0 && raw <= 100000) ? raw : (int)__int_as_float(raw);
    int steps = stepsv < 64 ? stepsv : 64;
    if (steps < 0) steps = 0;

    // ---- prologue ----
#pragma unroll
    for (int k = 0; k < 32; k++) {
        sm[OFF_KEYS + k * 1024 + tid]       = g_keys[k * NENT + (int)rank * 1024 + tid];
        sm[OFF_KEYS + k * 1024 + 512 + tid] = g_keys[k * NENT + (int)rank * 1024 + 512 + tid];
    }
    sm[OFF_MASK + tid]       = entity_mask[(int)rank * 1024 + tid];
    sm[OFF_MASK + 512 + tid] = entity_mask[(int)rank * 1024 + 512 + tid];
#pragma unroll
    for (int i = 0; i < 16; i++)
        sm[OFF_WA1 + i * 512 + tid] = W_a1[i * 512 + tid];
#pragma unroll
    for (int i = 0; i < 8; i++) {
        int idx = tid + i * 512;   // idx = k*128 + t
        sm[OFF_W3T + idx] = W_a3[((int)rank * 128 + (idx & 127)) * 32 + (idx >> 7)];
    }
    {   // gate weights, padded layout: [g][row stride 66][half*33 + col31]
        const float* gw4[4] = { W_f, W_i0, W_i1, W_o };
        for (int idx = tid; idx < 4 * 2048; idx += TPB) {
            int g = idx >> 11, rem = idx & 2047, r = rem >> 6, c = rem & 63;
            sm[OFF_WG + g * 2112 + r * 66 + (c >> 5) * 33 + (c & 31)] = gw4[g][rem];
        }
    }
    float ba3 = 0.f;
    if (tid < 128) {
        sm[OFF_ARS + tid] = ar_in[(int)rank * 128 + tid];
        ba3 = b_a3[(int)rank * 128 + tid];
    }
    if (tid < 32) {
        sm[OFF_Q + tid] = 0.f; sm[OFF_H + tid] = 0.f;
        sm[OFF_BIAS +       tid] = b_a1[tid];
        sm[OFF_BIAS + 32  + tid] = b_f[tid];
        sm[OFF_BIAS + 64  + tid] = b_i0[tid];
        sm[OFF_BIAS + 96  + tid] = b_i1[tid];
        sm[OFF_BIAS + 128 + tid] = b_o[tid];
        sm[OFF_BIAS + 160 + tid] = ln_g[tid];
        sm[OFF_BIAS + 192 + tid] = ln_b[tid];
    }
    if (tid == 0) sm[OFF_SCAL + 3] = 0.f;
    for (int rr = 0; rr < 16; rr++) {
        int row = wid * 16 + rr;
        float acc = 0.f;
#pragma unroll
        for (int i = 0; i < 8; i++) {
            int j = lane + (i << 5);
            if (j < UTYPE) acc += W_fe[row * UTYPE + j] * utype[j];
        }
        acc = wsum(acc);
        if (lane == 0) sm[OFF_C0 + row] = b_a0[row] + fmaxf(0.f, acc + b_fe[row]);
    }
    // register-pinned W_a0: thread owns row (tid>>1), half (tid&1)
    const int row2 = tid >> 1;
    const int half = tid & 1;
    float4 w16[16];
    {
        const float4* wp = (const float4*)(W_a0 + (size_t)row2 * ARDIM + (int)rank * 128 + half * 64);
#pragma unroll
        for (int j = 0; j < 16; j++) w16[j] = wp[j];
    }
    uint32_t pd0 = mapa_rank(smbase + (OFF_PART + (int)rank * 256) * 4u, (uint32_t)(half * 4 + 0));
    uint32_t pd1 = mapa_rank(smbase + (OFF_PART + (int)rank * 256) * 4u, (uint32_t)(half * 4 + 1));
    uint32_t pd2 = mapa_rank(smbase + (OFF_PART + (int)rank * 256) * 4u, (uint32_t)(half * 4 + 2));
    uint32_t pd3 = mapa_rank(smbase + (OFF_PART + (int)rank * 256) * 4u, (uint32_t)(half * 4 + 3));
    uint32_t mb_dst = mapa_rank(smbase + OFF_MB * 4u, (uint32_t)(lane & 7));
    cluster_sync_all();

    // ---- sequential steps ----
    for (int step = 0; step < steps; ++step) {
        __syncthreads();

        // S0: row-per-thread-pair GEMV from registers, 1 shfl, 4-rank scatter
        {
            const float4* ap = ((const float4*)(sm + OFF_ARS)) + (half << 4);
            float a0 = 0.f, a1 = 0.f, a2 = 0.f, a3 = 0.f;
#pragma unroll
            for (int j = 0; j < 16; j += 4) {
                float4 x0 = ap[j], x1 = ap[j + 1], x2 = ap[j + 2], x3 = ap[j + 3];
                a0 += w16[j].x     * x0.x + w16[j].y     * x0.y + w16[j].z     * x0.z + w16[j].w     * x0.w;
                a1 += w16[j + 1].x * x1.x + w16[j + 1].y * x1.y + w16[j + 1].z * x1.z + w16[j + 1].w * x1.w;
                a2 += w16[j + 2].x * x2.x + w16[j + 2].y * x2.y + w16[j + 2].z * x2.z + w16[j + 2].w * x2.w;
                a3 += w16[j + 3].x * x3.x + w16[j + 3].y * x3.y + w16[j + 3].z * x3.z + w16[j + 3].w * x3.w;
            }
            float acc = (a0 + a1) + (a2 + a3);
            acc += __shfl_xor_sync(FULLMASK, acc, 1);
            uint32_t off = (uint32_t)row2 * 4u;
            st_remote_f32(pd0 + off, acc);
            st_remote_f32(pd1 + off, acc);
            st_remote_f32(pd2 + off, acc);
            st_remote_f32(pd3 + off, acc);
        }
        cluster_sync_all();   // A

        // S1 (replicated): i0 -> relu -> i1 -> gates -> LSTM -> qn
        bool active = (sm[OFF_SCAL + 3] == 0.f);
        if (tid < 256) {
            float s = 0.f;
#pragma unroll
            for (int r = 0; r < 8; r++) s += sm[OFF_PART + r * 256 + tid];
            sm[OFF_A + tid] = fmaxf(0.f, s + sm[OFF_C0 + tid]);
        }
        __syncthreads();
        {   // i1: 2 rows/warp, dots first, then interleaved full reduction chains
            float acc0, acc1;
            {
                const float4* a4 = (const float4*)(sm + OFF_A);
                float4 x0 = a4[lane * 2], x1 = a4[lane * 2 + 1];
                const float4* wr0 = (const float4*)(sm + OFF_WA1 + (wid * 2) * EMB);
                const float4* wr1 = (const float4*)(sm + OFF_WA1 + (wid * 2 + 1) * EMB);
                float4 p0 = wr0[lane * 2], p1 = wr0[lane * 2 + 1];
                float4 q0 = wr1[lane * 2], q1 = wr1[lane * 2 + 1];
                acc0 = p0.x * x0.x + p0.y * x0.y + p0.z * x0.z + p0.w * x0.w
                     + p1.x * x1.x + p1.y * x1.y + p1.z * x1.z + p1.w * x1.w;
                acc1 = q0.x * x0.x + q0.y * x0.y + q0.z * x0.z + q0.w * x0.w
                     + q1.x * x1.x + q1.y * x1.y + q1.z * x1.z + q1.w * x1.w;
            }
#pragma unroll
            for (int o = 16; o > 0; o >>= 1) {
                acc0 += __shfl_xor_sync(FULLMASK, acc0, o);
                acc1 += __shfl_xor_sync(FULLMASK, acc1, o);
            }
            if (lane == 0) {
                sm[OFF_X + wid * 2]     = fmaxf(0.f, acc0 + sm[OFF_BIAS + wid * 2]);
                sm[OFF_X + wid * 2 + 1] = fmaxf(0.f, acc1 + sm[OFF_BIAS + wid * 2 + 1]);
            }
        }
        if (wid == 1) sm[OFF_X + 32 + lane] = sm[OFF_Q + lane];
        __syncthreads();
        // gates: 128 outputs over 256 threads, padded conflict-free layout, 1 shfl
        if (tid < 256) {
            int o = tid >> 1, hf = tid & 1;
            int g = o >> 5, row = o & 31;
            const float* wp = sm + OFF_WG + g * 2112 + row * 66 + hf * 33;
            const float* xp = sm + OFF_X + hf * 32;
            float a0 = 0.f, a1 = 0.f, a2 = 0.f, a3 = 0.f;
#pragma unroll
            for (int j = 0; j < 32; j += 4) {
                a0 += wp[j]     * xp[j];
                a1 += wp[j + 1] * xp[j + 1];
                a2 += wp[j + 2] * xp[j + 2];
                a3 += wp[j + 3] * xp[j + 3];
            }
            float acc = (a0 + a1) + (a2 + a3);
            acc += __shfl_xor_sync(FULLMASK, acc, 1);
            if (hf == 0) sm[OFF_G + g * 32 + row] = acc + sm[OFF_BIAS + 32 + g * 32 + row];
        }
        __syncthreads();
        if (wid == 0) {
            float g = sm[OFF_BIAS + 160 + lane], b = sm[OFF_BIAS + 192 + lane];
            float gF = sm[OFF_G + lane], g0v = sm[OFF_G + 32 + lane];
            float g1v = sm[OFF_G + 64 + lane], gO = sm[OFF_G + 96 + lane];
            float xF = fsig(gF);
            float xR = fsig(g0v) * ftanh(g1v);
            float xO = fsig(gO);
            float aF = xF, aR = xR, aO = xO;
            float qF = xF * xF, qR = xR * xR, qO = xO * xO;
#pragma unroll
            for (int o = 16; o > 0; o >>= 1) {
                aF += __shfl_xor_sync(FULLMASK, aF, o);
                aR += __shfl_xor_sync(FULLMASK, aR, o);
                aO += __shfl_xor_sync(FULLMASK, aO, o);
                qF += __shfl_xor_sync(FULLMASK, qF, o);
                qR += __shfl_xor_sync(FULLMASK, qR, o);
                qO += __shfl_xor_sync(FULLMASK, qO, o);
            }
            const float inv32 = 1.f / 32.f;
            float mF = aF * inv32, vF = qF * inv32 - mF * mF;
            float mR = aR * inv32, vR = qR * inv32 - mR * mR;
            float mO = aO * inv32, vO = qO * inv32 - mO * mO;
            float forget = (xF - mF) * rsqrtf(vF + 1e-5f) * g + b;
            float rem    = (xR - mR) * rsqrtf(vR + 1e-5f) * g + b;
            float outg   = (xO - mO) * rsqrtf(vO + 1e-5f) * g + b;
            float hn = rem + forget * sm[OFF_H + lane];
            float qn = ftanh(hn) * outg;
            sm[OFF_QN + lane] = qn;
            if (active) { sm[OFF_Q + lane] = qn; sm[OFF_H + lane] = hn; }
        }
        __syncthreads();

        // S2 (vectorized): 256 threads x 4 entities via LDS.128
        float v0 = 0.f, v1 = 0.f, v2 = 0.f, v3 = 0.f;
        if (tid < 256) {
            const float4* key4 = (const float4*)(sm + OFF_KEYS);
            float d0 = 0.f, d1 = 0.f, d2 = 0.f, d3 = 0.f;
#pragma unroll
            for (int k = 0; k < 32; k++) {
                float q = sm[OFF_QN + k];
                float4 kk = key4[k * 256 + tid];
                d0 += q * kk.x;
                d1 += q * kk.y;
                d2 += q * kk.z;
                d3 += q * kk.w;
            }
            v0 = __expf(__logf(1.f / (1.f + __expf(-d0))) * 1.25f);
            v1 = __expf(__logf(1.f / (1.f + __expf(-d1))) * 1.25f);
            v2 = __expf(__logf(1.f / (1.f + __expf(-d2))) * 1.25f);
            v3 = __expf(__logf(1.f / (1.f + __expf(-d3))) * 1.25f);
            float s = wsum(((v0 + v1) + (v2 + v3)));
            float base = (float)((int)rank * 1024 + tid * 4);
            float mv = v0, mi = base;
            if (v1 > mv) { mv = v1; mi = base + 1.f; }
            if (v2 > mv) { mv = v2; mi = base + 2.f; }
            if (v3 > mv) { mv = v3; mi = base + 3.f; }
            argmax_red(mv, mi);
            if (lane == 0) {
                sm[OFF_RED + wid * 3 + 0] = s;
                sm[OFF_RED + wid * 3 + 1] = mv;
                sm[OFF_RED + wid * 3 + 2] = mi;
            }
        }
        __syncthreads();
        if (wid == 0) {
            float s2 = (lane < 8) ? sm[OFF_RED + lane * 3 + 0] : 0.f;
            float m2 = (lane < 8) ? sm[OFF_RED + lane * 3 + 1] : -INFINITY;
            float i2 = (lane < 8) ? sm[OFF_RED + lane * 3 + 2] : 1e9f;
            // FULL 5-level interleaved reduce — all lanes end with the winner
#pragma unroll
            for (int o = 16; o > 0; o >>= 1) {
                s2 += __shfl_xor_sync(FULLMASK, s2, o);
                float ov = __shfl_xor_sync(FULLMASK, m2, o);
                float oi = __shfl_xor_sync(FULLMASK, i2, o);
                if (ov > m2 || (ov == m2 && oi < i2)) { m2 = ov; i2 = oi; }
            }
            int li = (int)i2 - (int)rank * 1024;
            float maskv = sm[OFF_MASK + li];
            float kv = sm[OFF_KEYS + lane * 1024 + li];
            uint32_t mbk_addr = smbase + (uint32_t)((OFF_MBK + (int)rank * 32 + lane) * 4);
#pragma unroll
            for (int rr = 0; rr < 8; rr++)
                st_remote_f32(mapa_rank(mbk_addr, (uint32_t)rr), kv);
            if (lane < 8) {
                st_remote_f32(mb_dst + ((uint32_t)rank) * 4u,        s2);
                st_remote_f32(mb_dst + (8u + (uint32_t)rank) * 4u,   m2);
                st_remote_f32(mb_dst + (16u + (uint32_t)rank) * 4u,  i2);
                st_remote_f32(mb_dst + (24u + (uint32_t)rank) * 4u,  maskv);
            }
        }
        cluster_sync_all();   // B

        // S3 (replicated): pick, selection from local MBK, mask/flags
        if (wid == 0) {
            float s  = (lane < 8) ? sm[OFF_MB + lane]      : 0.f;
            float m  = (lane < 8) ? sm[OFF_MB + 8 + lane]  : -INFINITY;
            float ix = (lane < 8) ? sm[OFF_MB + 16 + lane] : 1e9f;
#pragma unroll
            for (int o = 16; o > 0; o >>= 1) {
                s += __shfl_xor_sync(FULLMASK, s, o);
                float ov = __shfl_xor_sync(FULLMASK, m, o);
                float oi = __shfl_xor_sync(FULLMASK, ix, o);
                if (ov > m || (ov == m && oi < ix)) { m = ov; ix = oi; }
            }
            float ssum = s;
            int pick = (int)ix;
            int wrank = pick >> 10;
            bool act2  = (sm[OFF_SCAL + 3] == 0.f);
            bool valid = (ssum != 0.f);
            float rowinv = (act2 && valid) ? 1.f / ssum : 0.f;
            float selv = sm[OFF_MBK + wrank * 32 + lane];
            float mean = wsum(selv) * (1.f / 32.f);
            float cen = selv - mean;
            bool nanfree = (__ballot_sync(FULLMASK, isnan(cen)) == 0u);
            bool hit = act2 && valid && (sm[OFF_MB + 24 + wrank] != 0.f);
            sm[OFF_CENT + lane] = cen;
            if (lane == 0) {
                sm[OFF_SCAL + 0] = rowinv;
                sm[OFF_SCAL + 2] = (hit && nanfree) ? 1.f : 0.f;
                if (hit) {
                    if (wrank == (int)rank) sm[OFF_MASK + (pick & 1023)] = 0.f;
                    if (rank == 0) out[(size_t)NENT * NENT + pick] = 1.f;
                }
                if (hit && !nanfree) sm[OFF_SCAL + 3] = 1.f;
            }
        }
        __syncthreads();

        // S4: vectorized row write + local ar-slice update
        if (tid < 256) {
            float rowinv = sm[OFF_SCAL + 0];
            float4* orow = (float4*)(out + (size_t)step * NENT + (int)rank * 1024);
            orow[tid] = make_float4(v0 * rowinv, v1 * rowinv, v2 * rowinv, v3 * rowinv);
        }
        if (sm[OFF_SCAL + 2] != 0.f && tid < 128) {
            float d = 0.f;
#pragma unroll
            for (int k = 0; k < 32; k++) d += sm[OFF_W3T + k * 128 + tid] * sm[OFF_CENT + k];
            sm[OFF_ARS + tid] += fmaxf(0.f, d + ba3);
        }
    }

    __syncthreads();
    if (tid < 128)
        out[(size_t)NENT * NENT + NENT + (int)rank * 128 + tid] = sm[OFF_ARS + tid];
}

extern "C" void kernel_launch(void* const* d_in, const int* in_sizes, int n_in,
                              void* d_out, int out_size) {
    const float* utype = (const float*)d_in[0];
    const float* emask = (const float*)d_in[1];
    const float* enc   = (const float*)d_in[2];
    const float* ar    = (const float*)d_in[3];
    const float* W_fe  = (const float*)d_in[4];
    const float* b_fe  = (const float*)d_in[5];
    const float* W_k   = (const float*)d_in[6];
    const float* b_k   = (const float*)d_in[7];
    const float* W_a0  = (const float*)d_in[8];
    const float* b_a0  = (const float*)d_in[9];
    const float* W_a1  = (const float*)d_in[10];
    const float* b_a1  = (const float*)d_in[11];
    const float* W_f   = (const float*)d_in[12];
    const float* b_f   = (const float*)d_in[13];
    const float* W_i0  = (const float*)d_in[14];
    const float* b_i0  = (const float*)d_in[15];
    const float* W_i1  = (const float*)d_in[16];
    const float* b_i1  = (const float*)d_in[17];
    const float* W_o   = (const float*)d_in[18];
    const float* b_o   = (const float*)d_in[19];
    const float* ln_g  = (const float*)d_in[20];
    const float* ln_b  = (const float*)d_in[21];
    const float* W_a3  = (const float*)d_in[22];
    const float* b_a3  = (const float*)d_in[23];
    const int*   steps = (const int*)d_in[24];
    float* out = (float*)d_out;

    int total4 = out_size / 4;
    zk_kernel<<<1024 + 6144, 256>>>((const float4*)W_k, b_k, (const float4*)enc,
                                    (float4*)out, total4);
    cudaFuncSetAttribute(seq_kernel, cudaFuncAttributeMaxDynamicSharedMemorySize, SMEM_BYTES);
    seq_kernel<<<CL, TPB, SMEM_BYTES>>>(out, steps, emask, ar, utype,
                                        W_fe, b_fe, W_a0, b_a0, W_a1, b_a1,
                                        W_f, b_f, W_i0, b_i0, W_i1, b_i1,
                                        W_o, b_o, ln_g, ln_b, W_a3, b_a3);
}

// round 15
// speedup vs baseline: 1.0346x; 1.0223x over previous
#include <cuda_runtime.h>
#include <cstdint>
#include <math.h>

#define FULLMASK 0xffffffffu
#define NENT   8192
#define EMB    256
#define ARDIM  1024
#define UTYPE  233
#define CL     8
#define TPB    512

// ---- smem layout (float offsets) ----
#define OFF_KEYS   0        // 32768
#define OFF_WA1    32768    // 8192
#define OFF_W3T    40960    // 4096
#define OFF_PART   45056    // 2048
#define OFF_WG     47104    // 8448 = 4 gates x 32 rows x stride 66
#define OFF_MASK   55552    // 1024
#define OFF_MBK    56576    // 256
#define OFF_ARS    56832    // 128
#define OFF_C0     56960    // 256
#define OFF_A      57216    // 256
#define OFF_X      57472    // 64
#define OFF_Q      57536    // 32
#define OFF_H      57568    // 32
#define OFF_QN     57600    // 32
#define OFF_G      57632    // 128
#define OFF_MB     57792    // 32: sums[8], maxv[8], maxi[8], maskv[8]
#define OFF_RED    57824    // 48
#define OFF_BIAS   57872    // 224
#define OFF_SCAL   58096    // 4 ([3] = done flag)
#define SMEM_FLOATS 58100
#define SMEM_BYTES (SMEM_FLOATS * 4)

static __device__ float g_keys[32 * NENT];   // k-major

// ---------------- helpers ----------------
__device__ __forceinline__ uint32_t smem_u32(const void* p) {
    return (uint32_t)__cvta_generic_to_shared(p);
}
__device__ __forceinline__ uint32_t mapa_rank(uint32_t addr, uint32_t rank) {
    uint32_t r;
    asm volatile("mapa.shared::cluster.u32 %0, %1, %2;" : "=r"(r) : "r"(addr), "r"(rank));
    return r;
}
__device__ __forceinline__ void st_remote_f32(uint32_t addr, float v) {
    asm volatile("st.shared::cluster.f32 [%0], %1;" :: "r"(addr), "f"(v));
}
__device__ __forceinline__ void cluster_sync_all() {
    asm volatile("barrier.cluster.arrive.aligned;" ::: "memory");
    asm volatile("barrier.cluster.wait.aligned;" ::: "memory");
}
__device__ __forceinline__ uint32_t ctarank() {
    uint32_t r;
    asm("mov.u32 %0, %%cluster_ctarank;" : "=r"(r));
    return r;
}
__device__ __forceinline__ float wsum(float x) {
#pragma unroll
    for (int o = 16; o > 0; o >>= 1) x += __shfl_xor_sync(FULLMASK, x, o);
    return x;
}
__device__ __forceinline__ void argmax_red(float& v, float& idx) {
#pragma unroll
    for (int o = 16; o > 0; o >>= 1) {
        float ov = __shfl_xor_sync(FULLMASK, v, o);
        float oi = __shfl_xor_sync(FULLMASK, idx, o);
        if (ov > v || (ov == v && oi < idx)) { v = ov; idx = oi; }
    }
}
__device__ __forceinline__ float fsig(float x) {
    return __fdividef(1.f, 1.f + __expf(-x));
}
__device__ __forceinline__ float ftanh(float x) {
    x = fminf(fmaxf(x, -15.f), 15.f);
    float e = __expf(2.f * x);
    return __fdividef(e - 1.f, e + 1.f);
}
// sig(d)^1.25 = exp(-1.25*log(1+exp(-d)))  — 3 MUFU, no divide
__device__ __forceinline__ float vpow(float d) {
    return __expf(-1.25f * __logf(1.f + __expf(-d)));
}

// ---------------- fused zero-fill + keys ----------------
__global__ void __launch_bounds__(256) zk_kernel(const float4* __restrict__ Wk,
                                                 const float* __restrict__ bk,
                                                 const float4* __restrict__ enc,
                                                 float4* __restrict__ out4,
                                                 int total4) {
    if (blockIdx.x < 1024) {
        int g = blockIdx.x * 256 + threadIdx.x;
        int e = g >> 5;
        int lane = g & 31;
        const float4* er = enc + (size_t)e * 64;
        const float4* wr = Wk + (size_t)lane * 64;
        float acc = 0.f;
#pragma unroll 8
        for (int j = 0; j < 64; j++) {
            float4 a = er[j];
            float4 b = wr[j];
            acc += a.x * b.x + a.y * b.y + a.z * b.z + a.w * b.w;
        }
        g_keys[lane * NENT + e] = acc + bk[lane];
    } else {
        const float4 z = make_float4(0.f, 0.f, 0.f, 0.f);
        int nz = (gridDim.x - 1024) * 256;
        for (int i = (blockIdx.x - 1024) * 256 + threadIdx.x; i < total4; i += nz)
            __stcs(&out4[i], z);
    }
}

// ---------------- persistent sequential cluster kernel ----------------
__global__ void __cluster_dims__(CL, 1, 1) __launch_bounds__(TPB, 1)
seq_kernel(float* __restrict__ out,
           const int* __restrict__ p_steps,
           const float* __restrict__ entity_mask,
           const float* __restrict__ ar_in,
           const float* __restrict__ utype,
           const float* __restrict__ W_fe, const float* __restrict__ b_fe,
           const float* __restrict__ W_a0, const float* __restrict__ b_a0,
           const float* __restrict__ W_a1, const float* __restrict__ b_a1,
           const float* __restrict__ W_f,  const float* __restrict__ b_f,
           const float* __restrict__ W_i0, const float* __restrict__ b_i0,
           const float* __restrict__ W_i1, const float* __restrict__ b_i1,
           const float* __restrict__ W_o,  const float* __restrict__ b_o,
           const float* __restrict__ ln_g, const float* __restrict__ ln_b,
           const float* __restrict__ W_a3, const float* __restrict__ b_a3)
{
    extern __shared__ float sm[];
    const int tid  = threadIdx.x;
    const int lane = tid & 31;
    const int wid  = tid >> 5;
    const uint32_t rank = ctarank();
    const uint32_t smbase = smem_u32(sm);

    int raw = p_steps[0];
    int stepsv = (raw >= 0 && raw <= 100000) ? raw : (int)__int_as_float(raw);
    int steps = stepsv < 64 ? stepsv : 64;
    if (steps < 0) steps = 0;

    // ---- prologue ----
#pragma unroll
    for (int k = 0; k < 32; k++) {
        sm[OFF_KEYS + k * 1024 + tid]       = g_keys[k * NENT + (int)rank * 1024 + tid];
        sm[OFF_KEYS + k * 1024 + 512 + tid] = g_keys[k * NENT + (int)rank * 1024 + 512 + tid];
    }
    sm[OFF_MASK + tid]       = entity_mask[(int)rank * 1024 + tid];
    sm[OFF_MASK + 512 + tid] = entity_mask[(int)rank * 1024 + 512 + tid];
#pragma unroll
    for (int i = 0; i < 16; i++)
        sm[OFF_WA1 + i * 512 + tid] = W_a1[i * 512 + tid];
#pragma unroll
    for (int i = 0; i < 8; i++) {
        int idx = tid + i * 512;   // idx = k*128 + t
        sm[OFF_W3T + idx] = W_a3[((int)rank * 128 + (idx & 127)) * 32 + (idx >> 7)];
    }
    {   // gate weights, padded layout: [g][row stride 66][half*33 + col31]
        const float* gw4[4] = { W_f, W_i0, W_i1, W_o };
        for (int idx = tid; idx < 4 * 2048; idx += TPB) {
            int g = idx >> 11, rem = idx & 2047, r = rem >> 6, c = rem & 63;
            sm[OFF_WG + g * 2112 + r * 66 + (c >> 5) * 33 + (c & 31)] = gw4[g][rem];
        }
    }
    float ba3 = 0.f;
    if (tid < 128) {
        sm[OFF_ARS + tid] = ar_in[(int)rank * 128 + tid];
        ba3 = b_a3[(int)rank * 128 + tid];
    }
    if (tid < 32) {
        sm[OFF_Q + tid] = 0.f; sm[OFF_H + tid] = 0.f;
        sm[OFF_BIAS +       tid] = b_a1[tid];
        sm[OFF_BIAS + 32  + tid] = b_f[tid];
        sm[OFF_BIAS + 64  + tid] = b_i0[tid];
        sm[OFF_BIAS + 96  + tid] = b_i1[tid];
        sm[OFF_BIAS + 128 + tid] = b_o[tid];
        sm[OFF_BIAS + 160 + tid] = ln_g[tid];
        sm[OFF_BIAS + 192 + tid] = ln_b[tid];
    }
    if (tid == 0) sm[OFF_SCAL + 3] = 0.f;
    for (int rr = 0; rr < 16; rr++) {
        int row = wid * 16 + rr;
        float acc = 0.f;
#pragma unroll
        for (int i = 0; i < 8; i++) {
            int j = lane + (i << 5);
            if (j < UTYPE) acc += W_fe[row * UTYPE + j] * utype[j];
        }
        acc = wsum(acc);
        if (lane == 0) sm[OFF_C0 + row] = b_a0[row] + fmaxf(0.f, acc + b_fe[row]);
    }
    // register-pinned W_a0: thread owns row (tid>>1), half (tid&1)
    const int row2 = tid >> 1;
    const int half = tid & 1;
    float4 w16[16];
    {
        const float4* wp = (const float4*)(W_a0 + (size_t)row2 * ARDIM + (int)rank * 128 + half * 64);
#pragma unroll
        for (int j = 0; j < 16; j++) w16[j] = wp[j];
    }
    uint32_t pd0 = mapa_rank(smbase + (OFF_PART + (int)rank * 256) * 4u, (uint32_t)(half * 4 + 0));
    uint32_t pd1 = mapa_rank(smbase + (OFF_PART + (int)rank * 256) * 4u, (uint32_t)(half * 4 + 1));
    uint32_t pd2 = mapa_rank(smbase + (OFF_PART + (int)rank * 256) * 4u, (uint32_t)(half * 4 + 2));
    uint32_t pd3 = mapa_rank(smbase + (OFF_PART + (int)rank * 256) * 4u, (uint32_t)(half * 4 + 3));
    uint32_t mb_dst = mapa_rank(smbase + OFF_MB * 4u, (uint32_t)(lane & 7));
    cluster_sync_all();

    // ---- sequential steps (6 block barriers + 2 cluster syncs per step) ----
    for (int step = 0; step < steps; ++step) {
        // S0: row-per-thread-pair GEMV from registers, 1 shfl, 4-rank scatter
        // (ARS protected by the loop-end barrier / prologue cluster sync)
        {
            const float4* ap = ((const float4*)(sm + OFF_ARS)) + (half << 4);
            float a0 = 0.f, a1 = 0.f, a2 = 0.f, a3 = 0.f;
#pragma unroll
            for (int j = 0; j < 16; j += 4) {
                float4 x0 = ap[j], x1 = ap[j + 1], x2 = ap[j + 2], x3 = ap[j + 3];
                a0 += w16[j].x     * x0.x + w16[j].y     * x0.y + w16[j].z     * x0.z + w16[j].w     * x0.w;
                a1 += w16[j + 1].x * x1.x + w16[j + 1].y * x1.y + w16[j + 1].z * x1.z + w16[j + 1].w * x1.w;
                a2 += w16[j + 2].x * x2.x + w16[j + 2].y * x2.y + w16[j + 2].z * x2.z + w16[j + 2].w * x2.w;
                a3 += w16[j + 3].x * x3.x + w16[j + 3].y * x3.y + w16[j + 3].z * x3.z + w16[j + 3].w * x3.w;
            }
            float acc = (a0 + a1) + (a2 + a3);
            acc += __shfl_xor_sync(FULLMASK, acc, 1);
            uint32_t off = (uint32_t)row2 * 4u;
            st_remote_f32(pd0 + off, acc);
            st_remote_f32(pd1 + off, acc);
            st_remote_f32(pd2 + off, acc);
            st_remote_f32(pd3 + off, acc);
        }
        cluster_sync_all();   // A

        // latch done flag (pre any write this step; used by LSTM + S3)
        bool active = (sm[OFF_SCAL + 3] == 0.f);

        // S1: i0 -> relu -> i1 -> gates -> LSTM -> qn
        if (tid < 256) {
            float s = 0.f;
#pragma unroll
            for (int r = 0; r < 8; r++) s += sm[OFF_PART + r * 256 + tid];
            sm[OFF_A + tid] = fmaxf(0.f, s + sm[OFF_C0 + tid]);
        }
        __syncthreads();   // (1)
        {   // i1: 2 rows/warp, interleaved reduction chains
            float acc0, acc1;
            {
                const float4* a4 = (const float4*)(sm + OFF_A);
                float4 x0 = a4[lane * 2], x1 = a4[lane * 2 + 1];
                const float4* wr0 = (const float4*)(sm + OFF_WA1 + (wid * 2) * EMB);
                const float4* wr1 = (const float4*)(sm + OFF_WA1 + (wid * 2 + 1) * EMB);
                float4 p0 = wr0[lane * 2], p1 = wr0[lane * 2 + 1];
                float4 q0 = wr1[lane * 2], q1 = wr1[lane * 2 + 1];
                acc0 = p0.x * x0.x + p0.y * x0.y + p0.z * x0.z + p0.w * x0.w
                     + p1.x * x1.x + p1.y * x1.y + p1.z * x1.z + p1.w * x1.w;
                acc1 = q0.x * x0.x + q0.y * x0.y + q0.z * x0.z + q0.w * x0.w
                     + q1.x * x1.x + q1.y * x1.y + q1.z * x1.z + q1.w * x1.w;
            }
#pragma unroll
            for (int o = 16; o > 0; o >>= 1) {
                acc0 += __shfl_xor_sync(FULLMASK, acc0, o);
                acc1 += __shfl_xor_sync(FULLMASK, acc1, o);
            }
            if (lane == 0) {
                sm[OFF_X + wid * 2]     = fmaxf(0.f, acc0 + sm[OFF_BIAS + wid * 2]);
                sm[OFF_X + wid * 2 + 1] = fmaxf(0.f, acc1 + sm[OFF_BIAS + wid * 2 + 1]);
            }
        }
        if (wid == 1) sm[OFF_X + 32 + lane] = sm[OFF_Q + lane];
        __syncthreads();   // (2)
        if (tid < 256) {   // gates: conflict-free padded layout, 1 shfl
            int o = tid >> 1, hf = tid & 1;
            int g = o >> 5, row = o & 31;
            const float* wp = sm + OFF_WG + g * 2112 + row * 66 + hf * 33;
            const float* xp = sm + OFF_X + hf * 32;
            float a0 = 0.f, a1 = 0.f, a2 = 0.f, a3 = 0.f;
#pragma unroll
            for (int j = 0; j < 32; j += 4) {
                a0 += wp[j]     * xp[j];
                a1 += wp[j + 1] * xp[j + 1];
                a2 += wp[j + 2] * xp[j + 2];
                a3 += wp[j + 3] * xp[j + 3];
            }
            float acc = (a0 + a1) + (a2 + a3);
            acc += __shfl_xor_sync(FULLMASK, acc, 1);
            if (hf == 0) sm[OFF_G + g * 32 + row] = acc + sm[OFF_BIAS + 32 + g * 32 + row];
        }
        __syncthreads();   // (3)
        if (wid == 0) {
            float g = sm[OFF_BIAS + 160 + lane], b = sm[OFF_BIAS + 192 + lane];
            float gF = sm[OFF_G + lane], g0v = sm[OFF_G + 32 + lane];
            float g1v = sm[OFF_G + 64 + lane], gO = sm[OFF_G + 96 + lane];
            float xF = fsig(gF);
            float xR = fsig(g0v) * ftanh(g1v);
            float xO = fsig(gO);
            float aF = xF, aR = xR, aO = xO;
            float qF = xF * xF, qR = xR * xR, qO = xO * xO;
#pragma unroll
            for (int o = 16; o > 0; o >>= 1) {
                aF += __shfl_xor_sync(FULLMASK, aF, o);
                aR += __shfl_xor_sync(FULLMASK, aR, o);
                aO += __shfl_xor_sync(FULLMASK, aO, o);
                qF += __shfl_xor_sync(FULLMASK, qF, o);
                qR += __shfl_xor_sync(FULLMASK, qR, o);
                qO += __shfl_xor_sync(FULLMASK, qO, o);
            }
            const float inv32 = 1.f / 32.f;
            float mF = aF * inv32, vF = qF * inv32 - mF * mF;
            float mR = aR * inv32, vR = qR * inv32 - mR * mR;
            float mO = aO * inv32, vO = qO * inv32 - mO * mO;
            float forget = (xF - mF) * rsqrtf(vF + 1e-5f) * g + b;
            float rem    = (xR - mR) * rsqrtf(vR + 1e-5f) * g + b;
            float outg   = (xO - mO) * rsqrtf(vO + 1e-5f) * g + b;
            float hn = rem + forget * sm[OFF_H + lane];
            float qn = ftanh(hn) * outg;
            sm[OFF_QN + lane] = qn;
            if (active) { sm[OFF_Q + lane] = qn; sm[OFF_H + lane] = hn; }
        }
        __syncthreads();   // (4)

        // S2: 2 entities per thread + reductions + all-to-all mailbox
        float d0 = 0.f, d1 = 0.f;
#pragma unroll
        for (int k = 0; k < 32; k++) {
            float q = sm[OFF_QN + k];
            d0 += q * sm[OFF_KEYS + k * 1024 + tid];
            d1 += q * sm[OFF_KEYS + k * 1024 + 512 + tid];
        }
        float v0 = vpow(d0);
        float v1 = vpow(d1);
        {
            float s = wsum(v0 + v1);
            float mv, mi;
            if (v1 > v0) { mv = v1; mi = (float)((int)rank * 1024 + 512 + tid); }
            else         { mv = v0; mi = (float)((int)rank * 1024 + tid); }
            argmax_red(mv, mi);
            if (lane == 0) {
                sm[OFF_RED + wid * 3 + 0] = s;
                sm[OFF_RED + wid * 3 + 1] = mv;
                sm[OFF_RED + wid * 3 + 2] = mi;
            }
        }
        __syncthreads();   // (5)
        if (wid == 0) {
            float s2 = (lane < 16) ? sm[OFF_RED + lane * 3 + 0] : 0.f;
            float m2 = (lane < 16) ? sm[OFF_RED + lane * 3 + 1] : -INFINITY;
            float i2 = (lane < 16) ? sm[OFF_RED + lane * 3 + 2] : 1e9f;
#pragma unroll
            for (int o = 16; o > 0; o >>= 1) {
                s2 += __shfl_xor_sync(FULLMASK, s2, o);
                float ov = __shfl_xor_sync(FULLMASK, m2, o);
                float oi = __shfl_xor_sync(FULLMASK, i2, o);
                if (ov > m2 || (ov == m2 && oi < i2)) { m2 = ov; i2 = oi; }
            }
            int li = (int)i2 - (int)rank * 1024;
            float maskv = sm[OFF_MASK + li];
            float kv = sm[OFF_KEYS + lane * 1024 + li];
            uint32_t mbk_addr = smbase + (uint32_t)((OFF_MBK + (int)rank * 32 + lane) * 4);
#pragma unroll
            for (int rr = 0; rr < 8; rr++)
                st_remote_f32(mapa_rank(mbk_addr, (uint32_t)rr), kv);
            if (lane < 8) {
                st_remote_f32(mb_dst + ((uint32_t)rank) * 4u,        s2);
                st_remote_f32(mb_dst + (8u + (uint32_t)rank) * 4u,   m2);
                st_remote_f32(mb_dst + (16u + (uint32_t)rank) * 4u,  i2);
                st_remote_f32(mb_dst + (24u + (uint32_t)rank) * 4u,  maskv);
            }
        }
        cluster_sync_all();   // B

        // S3 (replicated in ALL warps — rowinv stays in registers):
        float rowinv;
        {
            float s  = (lane < 8) ? sm[OFF_MB + lane]      : 0.f;
            float m  = (lane < 8) ? sm[OFF_MB + 8 + lane]  : -INFINITY;
            float ix = (lane < 8) ? sm[OFF_MB + 16 + lane] : 1e9f;
#pragma unroll
            for (int o = 16; o > 0; o >>= 1) {
                s += __shfl_xor_sync(FULLMASK, s, o);
                float ov = __shfl_xor_sync(FULLMASK, m, o);
                float oi = __shfl_xor_sync(FULLMASK, ix, o);
                if (ov > m || (ov == m && oi < ix)) { m = ov; ix = oi; }
            }
            float ssum = s;
            int pick = (int)ix;
            int wrank = pick >> 10;
            bool valid = (ssum != 0.f);
            rowinv = (active && valid) ? 1.f / ssum : 0.f;
            // warps 0-3: cen + nanfree + own ARS slice update (no block barrier)
            if (wid < 4) {
                float selv = sm[OFF_MBK + wrank * 32 + lane];
                float mean = wsum(selv) * (1.f / 32.f);
                float cen = selv - mean;
                bool nanfree = (__ballot_sync(FULLMASK, isnan(cen)) == 0u);
                bool hit = active && valid && (sm[OFF_MB + 24 + wrank] != 0.f);
                if (wid == 0 && lane == 0) {
                    if (hit) {
                        if (wrank == (int)rank) sm[OFF_MASK + (pick & 1023)] = 0.f;
                        if (rank == 0) out[(size_t)NENT * NENT + pick] = 1.f;
                    }
                    if (hit && !nanfree) sm[OFF_SCAL + 3] = 1.f;
                }
                if (hit && nanfree) {
                    float d = 0.f;
#pragma unroll
                    for (int k = 0; k < 32; k++) {
                        float c = __shfl_sync(FULLMASK, cen, k);
                        d += sm[OFF_W3T + k * 128 + tid] * c;
                    }
                    sm[OFF_ARS + tid] += fmaxf(0.f, d + ba3);
                }
            }
        }
        // S4: row writes with register rowinv (all 512 threads)
        out[(size_t)step * NENT + (int)rank * 1024 + tid]       = v0 * rowinv;
        out[(size_t)step * NENT + (int)rank * 1024 + 512 + tid] = v1 * rowinv;
        __syncthreads();   // (6) — protects ARS / done flag for next S0/S1
    }

    if (tid < 128)
        out[(size_t)NENT * NENT + NENT + (int)rank * 128 + tid] = sm[OFF_ARS + tid];
}

extern "C" void kernel_launch(void* const* d_in, const int* in_sizes, int n_in,
                              void* d_out, int out_size) {
    const float* utype = (const float*)d_in[0];
    const float* emask = (const float*)d_in[1];
    const float* enc   = (const float*)d_in[2];
    const float* ar    = (const float*)d_in[3];
    const float* W_fe  = (const float*)d_in[4];
    const float* b_fe  = (const float*)d_in[5];
    const float* W_k   = (const float*)d_in[6];
    const float* b_k   = (const float*)d_in[7];
    const float* W_a0  = (const float*)d_in[8];
    const float* b_a0  = (const float*)d_in[9];
    const float* W_a1  = (const float*)d_in[10];
    const float* b_a1  = (const float*)d_in[11];
    const float* W_f   = (const float*)d_in[12];
    const float* b_f   = (const float*)d_in[13];
    const float* W_i0  = (const float*)d_in[14];
    const float* b_i0  = (const float*)d_in[15];
    const float* W_i1  = (const float*)d_in[16];
    const float* b_i1  = (const float*)d_in[17];
    const float* W_o   = (const float*)d_in[18];
    const float* b_o   = (const float*)d_in[19];
    const float* ln_g  = (const float*)d_in[20];
    const float* ln_b  = (const float*)d_in[21];
    const float* W_a3  = (const float*)d_in[22];
    const float* b_a3  = (const float*)d_in[23];
    const int*   steps = (const int*)d_in[24];
    float* out = (float*)d_out;

    int total4 = out_size / 4;
    zk_kernel<<<1024 + 6144, 256>>>((const float4*)W_k, b_k, (const float4*)enc,
                                    (float4*)out, total4);
    cudaFuncSetAttribute(seq_kernel, cudaFuncAttributeMaxDynamicSharedMemorySize, SMEM_BYTES);
    seq_kernel<<<CL, TPB, SMEM_BYTES>>>(out, steps, emask, ar, utype,
                                        W_fe, b_fe, W_a0, b_a0, W_a1, b_a1,
                                        W_f, b_f, W_i0, b_i0, W_i1, b_i1,
                                        W_o, b_o, ln_g, ln_b, W_a3, b_a3);
}

// round 16
// speedup vs baseline: 1.0864x; 1.0500x over previous
#include <cuda_runtime.h>
#include <cstdint>
#include <math.h>

#define FULLMASK 0xffffffffu
#define NENT   8192
#define EMB    256
#define ARDIM  1024
#define UTYPE  233
#define CL     8
#define TPB    512
#define NHELP  120
#define GRID   (8 + NHELP)

// ---- smem layout (float offsets) ----
#define OFF_KEYS   0        // 32768
#define OFF_WA1    32768    // 8192
#define OFF_W3T    40960    // 4096
#define OFF_PART   45056    // 2048
#define OFF_WG     47104    // 8448 = 4 gates x 32 rows x stride 66
#define OFF_MASK   55552    // 1024
#define OFF_MBK    56576    // 256
#define OFF_ARS    56832    // 128
#define OFF_C0     56960    // 256
#define OFF_A      57216    // 256
#define OFF_X      57472    // 64
#define OFF_Q      57536    // 32
#define OFF_H      57568    // 32
#define OFF_QN     57600    // 32
#define OFF_G      57632    // 128
#define OFF_MB     57792    // 32: sums[8], maxv[8], maxi[8], maskv[8]
#define OFF_RED    57824    // 48
#define OFF_BIAS   57872    // 224
#define OFF_SCAL   58096    // 4 ([3] = done flag)
#define SMEM_FLOATS 58100
#define SMEM_BYTES (SMEM_FLOATS * 4)

static __device__ float g_keys[32 * NENT];   // k-major

// ---------------- helpers ----------------
__device__ __forceinline__ uint32_t smem_u32(const void* p) {
    return (uint32_t)__cvta_generic_to_shared(p);
}
__device__ __forceinline__ uint32_t mapa_rank(uint32_t addr, uint32_t rank) {
    uint32_t r;
    asm volatile("mapa.shared::cluster.u32 %0, %1, %2;" : "=r"(r) : "r"(addr), "r"(rank));
    return r;
}
__device__ __forceinline__ void st_remote_f32(uint32_t addr, float v) {
    asm volatile("st.shared::cluster.f32 [%0], %1;" :: "r"(addr), "f"(v));
}
__device__ __forceinline__ void cluster_sync_all() {
    asm volatile("barrier.cluster.arrive.aligned;" ::: "memory");
    asm volatile("barrier.cluster.wait.aligned;" ::: "memory");
}
__device__ __forceinline__ uint32_t ctarank() {
    uint32_t r;
    asm("mov.u32 %0, %%cluster_ctarank;" : "=r"(r));
    return r;
}
__device__ __forceinline__ float wsum(float x) {
#pragma unroll
    for (int o = 16; o > 0; o >>= 1) x += __shfl_xor_sync(FULLMASK, x, o);
    return x;
}
__device__ __forceinline__ void argmax_red(float& v, float& idx) {
#pragma unroll
    for (int o = 16; o > 0; o >>= 1) {
        float ov = __shfl_xor_sync(FULLMASK, v, o);
        float oi = __shfl_xor_sync(FULLMASK, idx, o);
        if (ov > v || (ov == v && oi < idx)) { v = ov; idx = oi; }
    }
}
__device__ __forceinline__ float fsig(float x) {
    return __fdividef(1.f, 1.f + __expf(-x));
}
__device__ __forceinline__ float ftanh(float x) {
    x = fminf(fmaxf(x, -15.f), 15.f);
    float e = __expf(2.f * x);
    return __fdividef(e - 1.f, e + 1.f);
}
// sig(d)^1.25 = exp(-1.25*log(1+exp(-d)))
__device__ __forceinline__ float vpow(float d) {
    return __expf(-1.25f * __logf(1.f + __expf(-d)));
}
__device__ __forceinline__ int parse_steps(const int* p) {
    int raw = p[0];
    int s = (raw >= 0 && raw <= 100000) ? raw : (int)__int_as_float(raw);
    if (s > 64) s = 64;
    if (s < 0) s = 0;
    return s;
}

// ---------------- keys + sel-zero (small, serialized) ----------------
__global__ void __launch_bounds__(256) zk_kernel(const float4* __restrict__ Wk,
                                                 const float* __restrict__ bk,
                                                 const float4* __restrict__ enc,
                                                 float* __restrict__ out) {
    if (blockIdx.x < 1024) {
        int g = blockIdx.x * 256 + threadIdx.x;
        int e = g >> 5;
        int lane = g & 31;
        const float4* er = enc + (size_t)e * 64;
        const float4* wr = Wk + (size_t)lane * 64;
        float acc = 0.f;
#pragma unroll 8
        for (int j = 0; j < 64; j++) {
            float4 a = er[j];
            float4 b = wr[j];
            acc += a.x * b.x + a.y * b.y + a.z * b.z + a.w * b.w;
        }
        g_keys[lane * NENT + e] = acc + bk[lane];
    } else {
        int z = blockIdx.x - 1024;   // 0..7 zero the sel region
        float4* s4 = (float4*)(out + (size_t)NENT * NENT);
        s4[z * 256 + threadIdx.x] = make_float4(0.f, 0.f, 0.f, 0.f);
    }
}

// ---------------- fused persistent kernel: seq cluster + zero helpers ----------------
__global__ void __cluster_dims__(CL, 1, 1) __launch_bounds__(TPB, 1)
seq_kernel(float* __restrict__ out,
           const int* __restrict__ p_steps,
           const float* __restrict__ entity_mask,
           const float* __restrict__ ar_in,
           const float* __restrict__ utype,
           const float* __restrict__ W_fe, const float* __restrict__ b_fe,
           const float* __restrict__ W_a0, const float* __restrict__ b_a0,
           const float* __restrict__ W_a1, const float* __restrict__ b_a1,
           const float* __restrict__ W_f,  const float* __restrict__ b_f,
           const float* __restrict__ W_i0, const float* __restrict__ b_i0,
           const float* __restrict__ W_i1, const float* __restrict__ b_i1,
           const float* __restrict__ W_o,  const float* __restrict__ b_o,
           const float* __restrict__ ln_g, const float* __restrict__ ln_b,
           const float* __restrict__ W_a3, const float* __restrict__ b_a3)
{
    extern __shared__ float sm[];
    const int tid  = threadIdx.x;
    const int steps = parse_steps(p_steps);

    // ===== helper path: stream-zero rows [steps, NENT) — fully disjoint =====
    if (blockIdx.x >= 8) {
        int z = blockIdx.x - 8;
        float4* o4 = (float4*)out;
        size_t s4 = (size_t)steps * (NENT / 4);
        size_t t4 = (size_t)NENT * (NENT / 4);
        const float4 zz = make_float4(0.f, 0.f, 0.f, 0.f);
        for (size_t i = s4 + (size_t)z * TPB + tid; i < t4; i += (size_t)NHELP * TPB)
            __stcs(&o4[i], zz);
        return;
    }

    // ===== sequential path (cluster 0) — identical to the 393.7us champion =====
    const int lane = tid & 31;
    const int wid  = tid >> 5;
    const uint32_t rank = ctarank();
    const uint32_t smbase = smem_u32(sm);

    // ---- prologue ----
#pragma unroll
    for (int k = 0; k < 32; k++) {
        sm[OFF_KEYS + k * 1024 + tid]       = g_keys[k * NENT + (int)rank * 1024 + tid];
        sm[OFF_KEYS + k * 1024 + 512 + tid] = g_keys[k * NENT + (int)rank * 1024 + 512 + tid];
    }
    sm[OFF_MASK + tid]       = entity_mask[(int)rank * 1024 + tid];
    sm[OFF_MASK + 512 + tid] = entity_mask[(int)rank * 1024 + 512 + tid];
#pragma unroll
    for (int i = 0; i < 16; i++)
        sm[OFF_WA1 + i * 512 + tid] = W_a1[i * 512 + tid];
#pragma unroll
    for (int i = 0; i < 8; i++) {
        int idx = tid + i * 512;   // idx = k*128 + t
        sm[OFF_W3T + idx] = W_a3[((int)rank * 128 + (idx & 127)) * 32 + (idx >> 7)];
    }
    {   // gate weights, padded layout: [g][row stride 66][half*33 + col31]
        const float* gw4[4] = { W_f, W_i0, W_i1, W_o };
        for (int idx = tid; idx < 4 * 2048; idx += TPB) {
            int g = idx >> 11, rem = idx & 2047, r = rem >> 6, c = rem & 63;
            sm[OFF_WG + g * 2112 + r * 66 + (c >> 5) * 33 + (c & 31)] = gw4[g][rem];
        }
    }
    float ba3 = 0.f;
    if (tid < 128) {
        sm[OFF_ARS + tid] = ar_in[(int)rank * 128 + tid];
        ba3 = b_a3[(int)rank * 128 + tid];
    }
    if (tid < 32) {
        sm[OFF_Q + tid] = 0.f; sm[OFF_H + tid] = 0.f;
        sm[OFF_BIAS +       tid] = b_a1[tid];
        sm[OFF_BIAS + 32  + tid] = b_f[tid];
        sm[OFF_BIAS + 64  + tid] = b_i0[tid];
        sm[OFF_BIAS + 96  + tid] = b_i1[tid];
        sm[OFF_BIAS + 128 + tid] = b_o[tid];
        sm[OFF_BIAS + 160 + tid] = ln_g[tid];
        sm[OFF_BIAS + 192 + tid] = ln_b[tid];
    }
    if (tid == 0) sm[OFF_SCAL + 3] = 0.f;
    for (int rr = 0; rr < 16; rr++) {
        int row = wid * 16 + rr;
        float acc = 0.f;
#pragma unroll
        for (int i = 0; i < 8; i++) {
            int j = lane + (i << 5);
            if (j < UTYPE) acc += W_fe[row * UTYPE + j] * utype[j];
        }
        acc = wsum(acc);
        if (lane == 0) sm[OFF_C0 + row] = b_a0[row] + fmaxf(0.f, acc + b_fe[row]);
    }
    // register-pinned W_a0: thread owns row (tid>>1), half (tid&1)
    const int row2 = tid >> 1;
    const int half = tid & 1;
    float4 w16[16];
    {
        const float4* wp = (const float4*)(W_a0 + (size_t)row2 * ARDIM + (int)rank * 128 + half * 64);
#pragma unroll
        for (int j = 0; j < 16; j++) w16[j] = wp[j];
    }
    uint32_t pd0 = mapa_rank(smbase + (OFF_PART + (int)rank * 256) * 4u, (uint32_t)(half * 4 + 0));
    uint32_t pd1 = mapa_rank(smbase + (OFF_PART + (int)rank * 256) * 4u, (uint32_t)(half * 4 + 1));
    uint32_t pd2 = mapa_rank(smbase + (OFF_PART + (int)rank * 256) * 4u, (uint32_t)(half * 4 + 2));
    uint32_t pd3 = mapa_rank(smbase + (OFF_PART + (int)rank * 256) * 4u, (uint32_t)(half * 4 + 3));
    uint32_t mb_dst = mapa_rank(smbase + OFF_MB * 4u, (uint32_t)(lane & 7));
    cluster_sync_all();

    // ---- sequential steps (6 block barriers + 2 cluster syncs per step) ----
    for (int step = 0; step < steps; ++step) {
        // S0: row-per-thread-pair GEMV from registers, 1 shfl, 4-rank scatter
        {
            const float4* ap = ((const float4*)(sm + OFF_ARS)) + (half << 4);
            float a0 = 0.f, a1 = 0.f, a2 = 0.f, a3 = 0.f;
#pragma unroll
            for (int j = 0; j < 16; j += 4) {
                float4 x0 = ap[j], x1 = ap[j + 1], x2 = ap[j + 2], x3 = ap[j + 3];
                a0 += w16[j].x     * x0.x + w16[j].y     * x0.y + w16[j].z     * x0.z + w16[j].w     * x0.w;
                a1 += w16[j + 1].x * x1.x + w16[j + 1].y * x1.y + w16[j + 1].z * x1.z + w16[j + 1].w * x1.w;
                a2 += w16[j + 2].x * x2.x + w16[j + 2].y * x2.y + w16[j + 2].z * x2.z + w16[j + 2].w * x2.w;
                a3 += w16[j + 3].x * x3.x + w16[j + 3].y * x3.y + w16[j + 3].z * x3.z + w16[j + 3].w * x3.w;
            }
            float acc = (a0 + a1) + (a2 + a3);
            acc += __shfl_xor_sync(FULLMASK, acc, 1);
            uint32_t off = (uint32_t)row2 * 4u;
            st_remote_f32(pd0 + off, acc);
            st_remote_f32(pd1 + off, acc);
            st_remote_f32(pd2 + off, acc);
            st_remote_f32(pd3 + off, acc);
        }
        cluster_sync_all();   // A

        bool active = (sm[OFF_SCAL + 3] == 0.f);

        // S1: i0 -> relu -> i1 -> gates -> LSTM -> qn
        if (tid < 256) {
            float s = 0.f;
#pragma unroll
            for (int r = 0; r < 8; r++) s += sm[OFF_PART + r * 256 + tid];
            sm[OFF_A + tid] = fmaxf(0.f, s + sm[OFF_C0 + tid]);
        }
        __syncthreads();   // (1)
        {
            float acc0, acc1;
            {
                const float4* a4 = (const float4*)(sm + OFF_A);
                float4 x0 = a4[lane * 2], x1 = a4[lane * 2 + 1];
                const float4* wr0 = (const float4*)(sm + OFF_WA1 + (wid * 2) * EMB);
                const float4* wr1 = (const float4*)(sm + OFF_WA1 + (wid * 2 + 1) * EMB);
                float4 p0 = wr0[lane * 2], p1 = wr0[lane * 2 + 1];
                float4 q0 = wr1[lane * 2], q1 = wr1[lane * 2 + 1];
                acc0 = p0.x * x0.x + p0.y * x0.y + p0.z * x0.z + p0.w * x0.w
                     + p1.x * x1.x + p1.y * x1.y + p1.z * x1.z + p1.w * x1.w;
                acc1 = q0.x * x0.x + q0.y * x0.y + q0.z * x0.z + q0.w * x0.w
                     + q1.x * x1.x + q1.y * x1.y + q1.z * x1.z + q1.w * x1.w;
            }
#pragma unroll
            for (int o = 16; o > 0; o >>= 1) {
                acc0 += __shfl_xor_sync(FULLMASK, acc0, o);
                acc1 += __shfl_xor_sync(FULLMASK, acc1, o);
            }
            if (lane == 0) {
                sm[OFF_X + wid * 2]     = fmaxf(0.f, acc0 + sm[OFF_BIAS + wid * 2]);
                sm[OFF_X + wid * 2 + 1] = fmaxf(0.f, acc1 + sm[OFF_BIAS + wid * 2 + 1]);
            }
        }
        if (wid == 1) sm[OFF_X + 32 + lane] = sm[OFF_Q + lane];
        __syncthreads();   // (2)
        if (tid < 256) {
            int o = tid >> 1, hf = tid & 1;
            int g = o >> 5, row = o & 31;
            const float* wp = sm + OFF_WG + g * 2112 + row * 66 + hf * 33;
            const float* xp = sm + OFF_X + hf * 32;
            float a0 = 0.f, a1 = 0.f, a2 = 0.f, a3 = 0.f;
#pragma unroll
            for (int j = 0; j < 32; j += 4) {
                a0 += wp[j]     * xp[j];
                a1 += wp[j + 1] * xp[j + 1];
                a2 += wp[j + 2] * xp[j + 2];
                a3 += wp[j + 3] * xp[j + 3];
            }
            float acc = (a0 + a1) + (a2 + a3);
            acc += __shfl_xor_sync(FULLMASK, acc, 1);
            if (hf == 0) sm[OFF_G + g * 32 + row] = acc + sm[OFF_BIAS + 32 + g * 32 + row];
        }
        __syncthreads();   // (3)
        if (wid == 0) {
            float g = sm[OFF_BIAS + 160 + lane], b = sm[OFF_BIAS + 192 + lane];
            float gF = sm[OFF_G + lane], g0v = sm[OFF_G + 32 + lane];
            float g1v = sm[OFF_G + 64 + lane], gO = sm[OFF_G + 96 + lane];
            float xF = fsig(gF);
            float xR = fsig(g0v) * ftanh(g1v);
            float xO = fsig(gO);
            float aF = xF, aR = xR, aO = xO;
            float qF = xF * xF, qR = xR * xR, qO = xO * xO;
#pragma unroll
            for (int o = 16; o > 0; o >>= 1) {
                aF += __shfl_xor_sync(FULLMASK, aF, o);
                aR += __shfl_xor_sync(FULLMASK, aR, o);
                aO += __shfl_xor_sync(FULLMASK, aO, o);
                qF += __shfl_xor_sync(FULLMASK, qF, o);
                qR += __shfl_xor_sync(FULLMASK, qR, o);
                qO += __shfl_xor_sync(FULLMASK, qO, o);
            }
            const float inv32 = 1.f / 32.f;
            float mF = aF * inv32, vF = qF * inv32 - mF * mF;
            float mR = aR * inv32, vR = qR * inv32 - mR * mR;
            float mO = aO * inv32, vO = qO * inv32 - mO * mO;
            float forget = (xF - mF) * rsqrtf(vF + 1e-5f) * g + b;
            float rem    = (xR - mR) * rsqrtf(vR + 1e-5f) * g + b;
            float outg   = (xO - mO) * rsqrtf(vO + 1e-5f) * g + b;
            float hn = rem + forget * sm[OFF_H + lane];
            float qn = ftanh(hn) * outg;
            sm[OFF_QN + lane] = qn;
            if (active) { sm[OFF_Q + lane] = qn; sm[OFF_H + lane] = hn; }
        }
        __syncthreads();   // (4)

        // S2: 2 entities per thread + reductions + all-to-all mailbox
        float d0 = 0.f, d1 = 0.f;
#pragma unroll
        for (int k = 0; k < 32; k++) {
            float q = sm[OFF_QN + k];
            d0 += q * sm[OFF_KEYS + k * 1024 + tid];
            d1 += q * sm[OFF_KEYS + k * 1024 + 512 + tid];
        }
        float v0 = vpow(d0);
        float v1 = vpow(d1);
        {
            float s = wsum(v0 + v1);
            float mv, mi;
            if (v1 > v0) { mv = v1; mi = (float)((int)rank * 1024 + 512 + tid); }
            else         { mv = v0; mi = (float)((int)rank * 1024 + tid); }
            argmax_red(mv, mi);
            if (lane == 0) {
                sm[OFF_RED + wid * 3 + 0] = s;
                sm[OFF_RED + wid * 3 + 1] = mv;
                sm[OFF_RED + wid * 3 + 2] = mi;
            }
        }
        __syncthreads();   // (5)
        if (wid == 0) {
            float s2 = (lane < 16) ? sm[OFF_RED + lane * 3 + 0] : 0.f;
            float m2 = (lane < 16) ? sm[OFF_RED + lane * 3 + 1] : -INFINITY;
            float i2 = (lane < 16) ? sm[OFF_RED + lane * 3 + 2] : 1e9f;
#pragma unroll
            for (int o = 16; o > 0; o >>= 1) {
                s2 += __shfl_xor_sync(FULLMASK, s2, o);
                float ov = __shfl_xor_sync(FULLMASK, m2, o);
                float oi = __shfl_xor_sync(FULLMASK, i2, o);
                if (ov > m2 || (ov == m2 && oi < i2)) { m2 = ov; i2 = oi; }
            }
            int li = (int)i2 - (int)rank * 1024;
            float maskv = sm[OFF_MASK + li];
            float kv = sm[OFF_KEYS + lane * 1024 + li];
            uint32_t mbk_addr = smbase + (uint32_t)((OFF_MBK + (int)rank * 32 + lane) * 4);
#pragma unroll
            for (int rr = 0; rr < 8; rr++)
                st_remote_f32(mapa_rank(mbk_addr, (uint32_t)rr), kv);
            if (lane < 8) {
                st_remote_f32(mb_dst + ((uint32_t)rank) * 4u,        s2);
                st_remote_f32(mb_dst + (8u + (uint32_t)rank) * 4u,   m2);
                st_remote_f32(mb_dst + (16u + (uint32_t)rank) * 4u,  i2);
                st_remote_f32(mb_dst + (24u + (uint32_t)rank) * 4u,  maskv);
            }
        }
        cluster_sync_all();   // B

        // S3 (replicated in ALL warps — rowinv stays in registers)
        float rowinv;
        {
            float s  = (lane < 8) ? sm[OFF_MB + lane]      : 0.f;
            float m  = (lane < 8) ? sm[OFF_MB + 8 + lane]  : -INFINITY;
            float ix = (lane < 8) ? sm[OFF_MB + 16 + lane] : 1e9f;
#pragma unroll
            for (int o = 16; o > 0; o >>= 1) {
                s += __shfl_xor_sync(FULLMASK, s, o);
                float ov = __shfl_xor_sync(FULLMASK, m, o);
                float oi = __shfl_xor_sync(FULLMASK, ix, o);
                if (ov > m || (ov == m && oi < ix)) { m = ov; ix = oi; }
            }
            float ssum = s;
            int pick = (int)ix;
            int wrank = pick >> 10;
            bool valid = (ssum != 0.f);
            rowinv = (active && valid) ? 1.f / ssum : 0.f;
            if (wid < 4) {
                float selv = sm[OFF_MBK + wrank * 32 + lane];
                float mean = wsum(selv) * (1.f / 32.f);
                float cen = selv - mean;
                bool nanfree = (__ballot_sync(FULLMASK, isnan(cen)) == 0u);
                bool hit = active && valid && (sm[OFF_MB + 24 + wrank] != 0.f);
                if (wid == 0 && lane == 0) {
                    if (hit) {
                        if (wrank == (int)rank) sm[OFF_MASK + (pick & 1023)] = 0.f;
                        if (rank == 0) out[(size_t)NENT * NENT + pick] = 1.f;
                    }
                    if (hit && !nanfree) sm[OFF_SCAL + 3] = 1.f;
                }
                if (hit && nanfree) {
                    float d = 0.f;
#pragma unroll
                    for (int k = 0; k < 32; k++) {
                        float c = __shfl_sync(FULLMASK, cen, k);
                        d += sm[OFF_W3T + k * 128 + tid] * c;
                    }
                    sm[OFF_ARS + tid] += fmaxf(0.f, d + ba3);
                }
            }
        }
        // S4: row writes with register rowinv
        out[(size_t)step * NENT + (int)rank * 1024 + tid]       = v0 * rowinv;
        out[(size_t)step * NENT + (int)rank * 1024 + 512 + tid] = v1 * rowinv;
        __syncthreads();   // (6)
    }

    if (tid < 128)
        out[(size_t)NENT * NENT + NENT + (int)rank * 128 + tid] = sm[OFF_ARS + tid];
}

extern "C" void kernel_launch(void* const* d_in, const int* in_sizes, int n_in,
                              void* d_out, int out_size) {
    const float* utype = (const float*)d_in[0];
    const float* emask = (const float*)d_in[1];
    const float* enc   = (const float*)d_in[2];
    const float* ar    = (const float*)d_in[3];
    const float* W_fe  = (const float*)d_in[4];
    const float* b_fe  = (const float*)d_in[5];
    const float* W_k   = (const float*)d_in[6];
    const float* b_k   = (const float*)d_in[7];
    const float* W_a0  = (const float*)d_in[8];
    const float* b_a0  = (const float*)d_in[9];
    const float* W_a1  = (const float*)d_in[10];
    const float* b_a1  = (const float*)d_in[11];
    const float* W_f   = (const float*)d_in[12];
    const float* b_f   = (const float*)d_in[13];
    const float* W_i0  = (const float*)d_in[14];
    const float* b_i0  = (const float*)d_in[15];
    const float* W_i1  = (const float*)d_in[16];
    const float* b_i1  = (const float*)d_in[17];
    const float* W_o   = (const float*)d_in[18];
    const float* b_o   = (const float*)d_in[19];
    const float* ln_g  = (const float*)d_in[20];
    const float* ln_b  = (const float*)d_in[21];
    const float* W_a3  = (const float*)d_in[22];
    const float* b_a3  = (const float*)d_in[23];
    const int*   steps = (const int*)d_in[24];
    float* out = (float*)d_out;

    zk_kernel<<<1032, 256>>>((const float4*)W_k, b_k, (const float4*)enc, out);
    cudaFuncSetAttribute(seq_kernel, cudaFuncAttributeMaxDynamicSharedMemorySize, SMEM_BYTES);
    seq_kernel<<<GRID, TPB, SMEM_BYTES>>>(out, steps, emask, ar, utype,
                                          W_fe, b_fe, W_a0, b_a0, W_a1, b_a1,
                                          W_f, b_f, W_i0, b_i0, W_i1, b_i1,
                                          W_o, b_o, ln_g, ln_b, W_a3, b_a3);
}

// round 17
// speedup vs baseline: 1.2730x; 1.1718x over previous
#include <cuda_runtime.h>
#include <cstdint>
#include <math.h>

#define FULLMASK 0xffffffffu
#define NENT   8192
#define EMB    256
#define ARDIM  1024
#define UTYPE  233
#define CL     8
#define TPB    512
#define NHELP  120
#define GRID   (8 + NHELP)

// ---- smem layout (float offsets) ----
#define OFF_KEYS   0        // 32768
#define OFF_WA1    32768    // 8192
#define OFF_W3T    40960    // 4096
#define OFF_PART   45056    // 2048
#define OFF_WG     47104    // 8448 = 4 gates x 32 rows x stride 66
#define OFF_MASK   55552    // 1024
#define OFF_MBK    56576    // 256
#define OFF_ARS    56832    // 128
#define OFF_C0     56960    // 256
#define OFF_A      57216    // 256
#define OFF_X      57472    // 64
#define OFF_Q      57536    // 32
#define OFF_H      57568    // 32
#define OFF_QN     57600    // 32
#define OFF_G      57632    // 128
#define OFF_MB     57792    // 32: sums[8], maxv[8], maxi[8], maskv[8]
#define OFF_RED    57824    // 48
#define OFF_BIAS   57872    // 224
#define OFF_SCAL   58096    // 4 ([3] = done flag)
#define SMEM_FLOATS 58100
#define SMEM_BYTES (SMEM_FLOATS * 4)

static __device__ float g_keys[32 * NENT];   // k-major

// ---------------- helpers ----------------
__device__ __forceinline__ uint32_t smem_u32(const void* p) {
    return (uint32_t)__cvta_generic_to_shared(p);
}
__device__ __forceinline__ uint32_t mapa_rank(uint32_t addr, uint32_t rank) {
    uint32_t r;
    asm volatile("mapa.shared::cluster.u32 %0, %1, %2;" : "=r"(r) : "r"(addr), "r"(rank));
    return r;
}
__device__ __forceinline__ void st_remote_f32(uint32_t addr, float v) {
    asm volatile("st.shared::cluster.f32 [%0], %1;" :: "r"(addr), "f"(v));
}
__device__ __forceinline__ void cluster_sync_all() {
    asm volatile("barrier.cluster.arrive.aligned;" ::: "memory");
    asm volatile("barrier.cluster.wait.aligned;" ::: "memory");
}
__device__ __forceinline__ uint32_t ctarank() {
    uint32_t r;
    asm("mov.u32 %0, %%cluster_ctarank;" : "=r"(r));
    return r;
}
__device__ __forceinline__ float wsum(float x) {
#pragma unroll
    for (int o = 16; o > 0; o >>= 1) x += __shfl_xor_sync(FULLMASK, x, o);
    return x;
}
__device__ __forceinline__ void argmax_red(float& v, float& idx) {
#pragma unroll
    for (int o = 16; o > 0; o >>= 1) {
        float ov = __shfl_xor_sync(FULLMASK, v, o);
        float oi = __shfl_xor_sync(FULLMASK, idx, o);
        if (ov > v || (ov == v && oi < idx)) { v = ov; idx = oi; }
    }
}
__device__ __forceinline__ float fsig(float x) {
    return __fdividef(1.f, 1.f + __expf(-x));
}
__device__ __forceinline__ float ftanh(float x) {
    x = fminf(fmaxf(x, -15.f), 15.f);
    float e = __expf(2.f * x);
    return __fdividef(e - 1.f, e + 1.f);
}
// sig(d)^1.25 = exp(-1.25*log(1+exp(-d)))
__device__ __forceinline__ float vpow(float d) {
    return __expf(-1.25f * __logf(1.f + __expf(-d)));
}
__device__ __forceinline__ int parse_steps(const int* p) {
    int raw = p[0];
    int s = (raw >= 0 && raw <= 100000) ? raw : (int)__int_as_float(raw);
    if (s > 64) s = 64;
    if (s < 0) s = 0;
    return s;
}

// ---------------- keys (W_k staged in smem, transposed) + sel-zero ----------------
__global__ void __launch_bounds__(256) zk_kernel(const float4* __restrict__ Wk,
                                                 const float* __restrict__ bk,
                                                 const float4* __restrict__ enc,
                                                 float* __restrict__ out) {
    if (blockIdx.x < 256) {
        __shared__ float4 wk[64 * 32];   // wk[j4*32 + k] = W_k[k][4j..4j+3]
        int tid = threadIdx.x;
        for (int i = tid; i < 2048; i += 256) {
            int k = i >> 6, j4 = i & 63;
            wk[j4 * 32 + k] = Wk[k * 64 + j4];
        }
        __syncthreads();
        int lane = tid & 31, wid = tid >> 5;
        float bkv = bk[lane];
#pragma unroll
        for (int sub = 0; sub < 4; sub++) {
            int e = blockIdx.x * 32 + wid * 4 + sub;
            const float4* er = enc + (size_t)e * 64;
            float acc = 0.f;
#pragma unroll 8
            for (int j = 0; j < 64; j++) {
                float4 a = er[j];          // uniform across warp (broadcast)
                float4 b = wk[j * 32 + lane];
                acc += a.x * b.x + a.y * b.y + a.z * b.z + a.w * b.w;
            }
            g_keys[lane * NENT + e] = acc + bkv;
        }
    } else {
        int z = blockIdx.x - 256;   // 0..7 zero the sel region
        float4* s4 = (float4*)(out + (size_t)NENT * NENT);
        s4[z * 256 + threadIdx.x] = make_float4(0.f, 0.f, 0.f, 0.f);
    }
}

// ---------------- fused persistent kernel: seq cluster + zero helpers ----------------
__global__ void __cluster_dims__(CL, 1, 1) __launch_bounds__(TPB, 1)
seq_kernel(float* __restrict__ out,
           const int* __restrict__ p_steps,
           const float* __restrict__ entity_mask,
           const float* __restrict__ ar_in,
           const float* __restrict__ utype,
           const float* __restrict__ W_fe, const float* __restrict__ b_fe,
           const float* __restrict__ W_a0, const float* __restrict__ b_a0,
           const float* __restrict__ W_a1, const float* __restrict__ b_a1,
           const float* __restrict__ W_f,  const float* __restrict__ b_f,
           const float* __restrict__ W_i0, const float* __restrict__ b_i0,
           const float* __restrict__ W_i1, const float* __restrict__ b_i1,
           const float* __restrict__ W_o,  const float* __restrict__ b_o,
           const float* __restrict__ ln_g, const float* __restrict__ ln_b,
           const float* __restrict__ W_a3, const float* __restrict__ b_a3)
{
    extern __shared__ float sm[];
    const int tid  = threadIdx.x;
    const int steps = parse_steps(p_steps);

    // ===== helper path: stream-zero rows [steps, NENT) — fully disjoint =====
    if (blockIdx.x >= 8) {
        int z = blockIdx.x - 8;
        float4* o4 = (float4*)out;
        size_t s4 = (size_t)steps * (NENT / 4);
        size_t t4 = (size_t)NENT * (NENT / 4);
        const float4 zz = make_float4(0.f, 0.f, 0.f, 0.f);
        for (size_t i = s4 + (size_t)z * TPB + tid; i < t4; i += (size_t)NHELP * TPB)
            __stcs(&o4[i], zz);
        return;
    }

    // ===== sequential path (cluster 0) =====
    const int lane = tid & 31;
    const int wid  = tid >> 5;
    const uint32_t rank = ctarank();
    const uint32_t smbase = smem_u32(sm);

    // ---- prologue ----
#pragma unroll
    for (int k = 0; k < 32; k++) {
        sm[OFF_KEYS + k * 1024 + tid]       = g_keys[k * NENT + (int)rank * 1024 + tid];
        sm[OFF_KEYS + k * 1024 + 512 + tid] = g_keys[k * NENT + (int)rank * 1024 + 512 + tid];
    }
    sm[OFF_MASK + tid]       = entity_mask[(int)rank * 1024 + tid];
    sm[OFF_MASK + 512 + tid] = entity_mask[(int)rank * 1024 + 512 + tid];
#pragma unroll
    for (int i = 0; i < 16; i++)
        sm[OFF_WA1 + i * 512 + tid] = W_a1[i * 512 + tid];
#pragma unroll
    for (int i = 0; i < 8; i++) {
        int idx = tid + i * 512;   // idx = k*128 + t
        sm[OFF_W3T + idx] = W_a3[((int)rank * 128 + (idx & 127)) * 32 + (idx >> 7)];
    }
    {   // gate weights, padded layout: [g][row stride 66][half*33 + col31]
        const float* gw4[4] = { W_f, W_i0, W_i1, W_o };
        for (int idx = tid; idx < 4 * 2048; idx += TPB) {
            int g = idx >> 11, rem = idx & 2047, r = rem >> 6, c = rem & 63;
            sm[OFF_WG + g * 2112 + r * 66 + (c >> 5) * 33 + (c & 31)] = gw4[g][rem];
        }
    }
    float ba3 = 0.f;
    if (tid < 128) {
        sm[OFF_ARS + tid] = ar_in[(int)rank * 128 + tid];
        ba3 = b_a3[(int)rank * 128 + tid];
    }
    if (tid < 32) {
        sm[OFF_Q + tid] = 0.f; sm[OFF_H + tid] = 0.f;
        sm[OFF_BIAS +       tid] = b_a1[tid];
        sm[OFF_BIAS + 32  + tid] = b_f[tid];
        sm[OFF_BIAS + 64  + tid] = b_i0[tid];
        sm[OFF_BIAS + 96  + tid] = b_i1[tid];
        sm[OFF_BIAS + 128 + tid] = b_o[tid];
        sm[OFF_BIAS + 160 + tid] = ln_g[tid];
        sm[OFF_BIAS + 192 + tid] = ln_b[tid];
    }
    if (tid == 0) sm[OFF_SCAL + 3] = 0.f;
    for (int rr = 0; rr < 16; rr++) {
        int row = wid * 16 + rr;
        float acc = 0.f;
#pragma unroll
        for (int i = 0; i < 8; i++) {
            int j = lane + (i << 5);
            if (j < UTYPE) acc += W_fe[row * UTYPE + j] * utype[j];
        }
        acc = wsum(acc);
        if (lane == 0) sm[OFF_C0 + row] = b_a0[row] + fmaxf(0.f, acc + b_fe[row]);
    }
    // register-pinned W_a0: thread owns row (tid>>1), half (tid&1)
    const int row2 = tid >> 1;
    const int half = tid & 1;
    float4 w16[16];
    {
        const float4* wp = (const float4*)(W_a0 + (size_t)row2 * ARDIM + (int)rank * 128 + half * 64);
#pragma unroll
        for (int j = 0; j < 16; j++) w16[j] = wp[j];
    }
    uint32_t pd0 = mapa_rank(smbase + (OFF_PART + (int)rank * 256) * 4u, (uint32_t)(half * 4 + 0));
    uint32_t pd1 = mapa_rank(smbase + (OFF_PART + (int)rank * 256) * 4u, (uint32_t)(half * 4 + 1));
    uint32_t pd2 = mapa_rank(smbase + (OFF_PART + (int)rank * 256) * 4u, (uint32_t)(half * 4 + 2));
    uint32_t pd3 = mapa_rank(smbase + (OFF_PART + (int)rank * 256) * 4u, (uint32_t)(half * 4 + 3));
    uint32_t mb_dst = mapa_rank(smbase + OFF_MB * 4u, (uint32_t)(lane & 7));
    cluster_sync_all();

    // ---- sequential steps (6 block barriers + 2 cluster syncs per step) ----
    for (int step = 0; step < steps; ++step) {
        // S0: row-per-thread-pair GEMV from registers, 1 shfl, 4-rank scatter
        {
            const float4* ap = ((const float4*)(sm + OFF_ARS)) + (half << 4);
            float a0 = 0.f, a1 = 0.f, a2 = 0.f, a3 = 0.f;
#pragma unroll
            for (int j = 0; j < 16; j += 4) {
                float4 x0 = ap[j], x1 = ap[j + 1], x2 = ap[j + 2], x3 = ap[j + 3];
                a0 += w16[j].x     * x0.x + w16[j].y     * x0.y + w16[j].z     * x0.z + w16[j].w     * x0.w;
                a1 += w16[j + 1].x * x1.x + w16[j + 1].y * x1.y + w16[j + 1].z * x1.z + w16[j + 1].w * x1.w;
                a2 += w16[j + 2].x * x2.x + w16[j + 2].y * x2.y + w16[j + 2].z * x2.z + w16[j + 2].w * x2.w;
                a3 += w16[j + 3].x * x3.x + w16[j + 3].y * x3.y + w16[j + 3].z * x3.z + w16[j + 3].w * x3.w;
            }
            float acc = (a0 + a1) + (a2 + a3);
            acc += __shfl_xor_sync(FULLMASK, acc, 1);
            uint32_t off = (uint32_t)row2 * 4u;
            st_remote_f32(pd0 + off, acc);
            st_remote_f32(pd1 + off, acc);
            st_remote_f32(pd2 + off, acc);
            st_remote_f32(pd3 + off, acc);
        }
        cluster_sync_all();   // A

        bool active = (sm[OFF_SCAL + 3] == 0.f);

        // S1: i0 -> relu -> i1 -> gates -> LSTM -> qn
        if (tid < 256) {
            float s = 0.f;
#pragma unroll
            for (int r = 0; r < 8; r++) s += sm[OFF_PART + r * 256 + tid];
            sm[OFF_A + tid] = fmaxf(0.f, s + sm[OFF_C0 + tid]);
        }
        __syncthreads();   // (1)
        {
            float acc0, acc1;
            {
                const float4* a4 = (const float4*)(sm + OFF_A);
                float4 x0 = a4[lane * 2], x1 = a4[lane * 2 + 1];
                const float4* wr0 = (const float4*)(sm + OFF_WA1 + (wid * 2) * EMB);
                const float4* wr1 = (const float4*)(sm + OFF_WA1 + (wid * 2 + 1) * EMB);
                float4 p0 = wr0[lane * 2], p1 = wr0[lane * 2 + 1];
                float4 q0 = wr1[lane * 2], q1 = wr1[lane * 2 + 1];
                acc0 = p0.x * x0.x + p0.y * x0.y + p0.z * x0.z + p0.w * x0.w
                     + p1.x * x1.x + p1.y * x1.y + p1.z * x1.z + p1.w * x1.w;
                acc1 = q0.x * x0.x + q0.y * x0.y + q0.z * x0.z + q0.w * x0.w
                     + q1.x * x1.x + q1.y * x1.y + q1.z * x1.z + q1.w * x1.w;
            }
#pragma unroll
            for (int o = 16; o > 0; o >>= 1) {
                acc0 += __shfl_xor_sync(FULLMASK, acc0, o);
                acc1 += __shfl_xor_sync(FULLMASK, acc1, o);
            }
            if (lane == 0) {
                sm[OFF_X + wid * 2]     = fmaxf(0.f, acc0 + sm[OFF_BIAS + wid * 2]);
                sm[OFF_X + wid * 2 + 1] = fmaxf(0.f, acc1 + sm[OFF_BIAS + wid * 2 + 1]);
            }
        }
        if (wid == 1) sm[OFF_X + 32 + lane] = sm[OFF_Q + lane];
        __syncthreads();   // (2)
        if (tid < 256) {
            int o = tid >> 1, hf = tid & 1;
            int g = o >> 5, row = o & 31;
            const float* wp = sm + OFF_WG + g * 2112 + row * 66 + hf * 33;
            const float* xp = sm + OFF_X + hf * 32;
            float a0 = 0.f, a1 = 0.f, a2 = 0.f, a3 = 0.f;
#pragma unroll
            for (int j = 0; j < 32; j += 4) {
                a0 += wp[j]     * xp[j];
                a1 += wp[j + 1] * xp[j + 1];
                a2 += wp[j + 2] * xp[j + 2];
                a3 += wp[j + 3] * xp[j + 3];
            }
            float acc = (a0 + a1) + (a2 + a3);
            acc += __shfl_xor_sync(FULLMASK, acc, 1);
            if (hf == 0) sm[OFF_G + g * 32 + row] = acc + sm[OFF_BIAS + 32 + g * 32 + row];
        }
        __syncthreads();   // (3)
        if (wid == 0) {
            float g = sm[OFF_BIAS + 160 + lane], b = sm[OFF_BIAS + 192 + lane];
            float gF = sm[OFF_G + lane], g0v = sm[OFF_G + 32 + lane];
            float g1v = sm[OFF_G + 64 + lane], gO = sm[OFF_G + 96 + lane];
            float xF = fsig(gF);
            float xR = fsig(g0v) * ftanh(g1v);
            float xO = fsig(gO);
            float aF = xF, aR = xR, aO = xO;
            float qF = xF * xF, qR = xR * xR, qO = xO * xO;
#pragma unroll
            for (int o = 16; o > 0; o >>= 1) {
                aF += __shfl_xor_sync(FULLMASK, aF, o);
                aR += __shfl_xor_sync(FULLMASK, aR, o);
                aO += __shfl_xor_sync(FULLMASK, aO, o);
                qF += __shfl_xor_sync(FULLMASK, qF, o);
                qR += __shfl_xor_sync(FULLMASK, qR, o);
                qO += __shfl_xor_sync(FULLMASK, qO, o);
            }
            const float inv32 = 1.f / 32.f;
            float mF = aF * inv32, vF = qF * inv32 - mF * mF;
            float mR = aR * inv32, vR = qR * inv32 - mR * mR;
            float mO = aO * inv32, vO = qO * inv32 - mO * mO;
            float forget = (xF - mF) * rsqrtf(vF + 1e-5f) * g + b;
            float rem    = (xR - mR) * rsqrtf(vR + 1e-5f) * g + b;
            float outg   = (xO - mO) * rsqrtf(vO + 1e-5f) * g + b;
            float hn = rem + forget * sm[OFF_H + lane];
            float qn = ftanh(hn) * outg;
            sm[OFF_QN + lane] = qn;
            if (active) { sm[OFF_Q + lane] = qn; sm[OFF_H + lane] = hn; }
        }
        __syncthreads();   // (4)

        // S2: 2 entities per thread + reductions + all-to-all mailbox
        float d0 = 0.f, d1 = 0.f;
#pragma unroll
        for (int k = 0; k < 32; k++) {
            float q = sm[OFF_QN + k];
            d0 += q * sm[OFF_KEYS + k * 1024 + tid];
            d1 += q * sm[OFF_KEYS + k * 1024 + 512 + tid];
        }
        float v0 = vpow(d0);
        float v1 = vpow(d1);
        {
            float s = wsum(v0 + v1);
            float mv, mi;
            if (v1 > v0) { mv = v1; mi = (float)((int)rank * 1024 + 512 + tid); }
            else         { mv = v0; mi = (float)((int)rank * 1024 + tid); }
            argmax_red(mv, mi);
            if (lane == 0) {
                sm[OFF_RED + wid * 3 + 0] = s;
                sm[OFF_RED + wid * 3 + 1] = mv;
                sm[OFF_RED + wid * 3 + 2] = mi;
            }
        }
        __syncthreads();   // (5)
        if (wid == 0) {
            float s2 = (lane < 16) ? sm[OFF_RED + lane * 3 + 0] : 0.f;
            float m2 = (lane < 16) ? sm[OFF_RED + lane * 3 + 1] : -INFINITY;
            float i2 = (lane < 16) ? sm[OFF_RED + lane * 3 + 2] : 1e9f;
#pragma unroll
            for (int o = 16; o > 0; o >>= 1) {
                s2 += __shfl_xor_sync(FULLMASK, s2, o);
                float ov = __shfl_xor_sync(FULLMASK, m2, o);
                float oi = __shfl_xor_sync(FULLMASK, i2, o);
                if (ov > m2 || (ov == m2 && oi < i2)) { m2 = ov; i2 = oi; }
            }
            int li = (int)i2 - (int)rank * 1024;
            float maskv = sm[OFF_MASK + li];
            float kv = sm[OFF_KEYS + lane * 1024 + li];
            uint32_t mbk_addr = smbase + (uint32_t)((OFF_MBK + (int)rank * 32 + lane) * 4);
#pragma unroll
            for (int rr = 0; rr < 8; rr++)
                st_remote_f32(mapa_rank(mbk_addr, (uint32_t)rr), kv);
            if (lane < 8) {
                st_remote_f32(mb_dst + ((uint32_t)rank) * 4u,        s2);
                st_remote_f32(mb_dst + (8u + (uint32_t)rank) * 4u,   m2);
                st_remote_f32(mb_dst + (16u + (uint32_t)rank) * 4u,  i2);
                st_remote_f32(mb_dst + (24u + (uint32_t)rank) * 4u,  maskv);
            }
        }
        cluster_sync_all();   // B

        // S3 (replicated in ALL warps — rowinv stays in registers)
        float rowinv;
        {
            float s  = (lane < 8) ? sm[OFF_MB + lane]      : 0.f;
            float m  = (lane < 8) ? sm[OFF_MB + 8 + lane]  : -INFINITY;
            float ix = (lane < 8) ? sm[OFF_MB + 16 + lane] : 1e9f;
#pragma unroll
            for (int o = 16; o > 0; o >>= 1) {
                s += __shfl_xor_sync(FULLMASK, s, o);
                float ov = __shfl_xor_sync(FULLMASK, m, o);
                float oi = __shfl_xor_sync(FULLMASK, ix, o);
                if (ov > m || (ov == m && oi < ix)) { m = ov; ix = oi; }
            }
            float ssum = s;
            int pick = (int)ix;
            int wrank = pick >> 10;
            bool valid = (ssum != 0.f);
            rowinv = (active && valid) ? 1.f / ssum : 0.f;
            if (wid < 4) {
                float selv = sm[OFF_MBK + wrank * 32 + lane];
                float mean = wsum(selv) * (1.f / 32.f);
                float cen = selv - mean;
                bool nanfree = (__ballot_sync(FULLMASK, isnan(cen)) == 0u);
                bool hit = active && valid && (sm[OFF_MB + 24 + wrank] != 0.f);
                if (wid == 0 && lane == 0) {
                    if (hit) {
                        if (wrank == (int)rank) sm[OFF_MASK + (pick & 1023)] = 0.f;
                        if (rank == 0) out[(size_t)NENT * NENT + pick] = 1.f;
                    }
                    if (hit && !nanfree) sm[OFF_SCAL + 3] = 1.f;
                }
                if (hit && nanfree) {
                    float d = 0.f;
#pragma unroll
                    for (int k = 0; k < 32; k++) {
                        float c = __shfl_sync(FULLMASK, cen, k);
                        d += sm[OFF_W3T + k * 128 + tid] * c;
                    }
                    sm[OFF_ARS + tid] += fmaxf(0.f, d + ba3);
                }
            }
        }
        // S4: row writes with register rowinv
        out[(size_t)step * NENT + (int)rank * 1024 + tid]       = v0 * rowinv;
        out[(size_t)step * NENT + (int)rank * 1024 + 512 + tid] = v1 * rowinv;
        __syncthreads();   // (6)
    }

    if (tid < 128)
        out[(size_t)NENT * NENT + NENT + (int)rank * 128 + tid] = sm[OFF_ARS + tid];
}

extern "C" void kernel_launch(void* const* d_in, const int* in_sizes, int n_in,
                              void* d_out, int out_size) {
    const float* utype = (const float*)d_in[0];
    const float* emask = (const float*)d_in[1];
    const float* enc   = (const float*)d_in[2];
    const float* ar    = (const float*)d_in[3];
    const float* W_fe  = (const float*)d_in[4];
    const float* b_fe  = (const float*)d_in[5];
    const float* W_k   = (const float*)d_in[6];
    const float* b_k   = (const float*)d_in[7];
    const float* W_a0  = (const float*)d_in[8];
    const float* b_a0  = (const float*)d_in[9];
    const float* W_a1  = (const float*)d_in[10];
    const float* b_a1  = (const float*)d_in[11];
    const float* W_f   = (const float*)d_in[12];
    const float* b_f   = (const float*)d_in[13];
    const float* W_i0  = (const float*)d_in[14];
    const float* b_i0  = (const float*)d_in[15];
    const float* W_i1  = (const float*)d_in[16];
    const float* b_i1  = (const float*)d_in[17];
    const float* W_o   = (const float*)d_in[18];
    const float* b_o   = (const float*)d_in[19];
    const float* ln_g  = (const float*)d_in[20];
    const float* ln_b  = (const float*)d_in[21];
    const float* W_a3  = (const float*)d_in[22];
    const float* b_a3  = (const float*)d_in[23];
    const int*   steps = (const int*)d_in[24];
    float* out = (float*)d_out;

    zk_kernel<<<264, 256>>>((const float4*)W_k, b_k, (const float4*)enc, out);
    cudaFuncSetAttribute(seq_kernel, cudaFuncAttributeMaxDynamicSharedMemorySize, SMEM_BYTES);
    seq_kernel<<<GRID, TPB, SMEM_BYTES>>>(out, steps, emask, ar, utype,
                                          W_fe, b_fe, W_a0, b_a0, W_a1, b_a1,
                                          W_f, b_f, W_i0, b_i0, W_i1, b_i1,
                                          W_o, b_o, ln_g, ln_b, W_a3, b_a3);
}